// round 11
// baseline (speedup 1.0000x reference)
#include <cuda_runtime.h>
#include <math.h>
#include <stdint.h>

// Problem constants
#define BATCH 32
#define NTOK  784
#define DIM   512
#define NH    8
#define HD    64
#define HH    28
#define WW    28
#define DA    49

typedef unsigned long long u64;

// -------- scratch (__device__ globals; no allocations allowed) --------
// head-planar activations: [b][h][n][d]
__device__ float    g_qh[BATCH * NH * NTOK * HD];
__device__ float    g_k [BATCH * NH * NTOK * HD];
__device__ float    g_v [BATCH * NH * NTOK * HD];
__device__ float    g_pos_bias[NH * DA * NTOK];        // [h,a,n]
__device__ float    g_agent_bias_t[NH * DA * NTOK];    // [h,a,n]
__device__ uint32_t g_xt   [BATCH * NTOK * DIM];
__device__ uint32_t g_qkvw_t[3 * DIM * DIM];           // q_w then kv_w [1536][512]
__device__ uint32_t g_pw_t [DIM * DIM];
__device__ uint32_t g_attn_t[BATCH * NTOK * DIM];      // tf32 attn+dwc (proj input)

__device__ __forceinline__ uint32_t f2tf(float f) {
    uint32_t u;
    asm("cvt.rna.tf32.f32 %0, %1;" : "=r"(u) : "f"(f));
    return u;
}
__device__ __forceinline__ void fma2(u64& d, u64 a, u64 b) {
    asm("fma.rn.f32x2 %0, %1, %2, %0;" : "+l"(d) : "l"(a), "l"(b));
}
__device__ __forceinline__ float2 unpack2(u64 v) {
    float2 f;
    asm("mov.b64 {%0,%1}, %2;" : "=f"(f.x), "=f"(f.y) : "l"(v));
    return f;
}
__device__ __forceinline__ u64 pack2(float lo, float hi) {
    u64 r;
    asm("mov.b64 %0, {%1,%2};" : "=l"(r) : "f"(lo), "f"(hi));
    return r;
}

// ======================= fp32 -> tf32 conversion (all operands, one kernel) =======================
__global__ void cvt_all(const float4* __restrict__ x, const float4* __restrict__ qw,
                        const float4* __restrict__ kvw, const float4* __restrict__ pw)
{
    const float4* src;
    uint4* dst;
    int n4;
    switch (blockIdx.y) {
        case 0: src = x;   dst = (uint4*)g_xt;                 n4 = BATCH * NTOK * DIM / 4; break;
        case 1: src = qw;  dst = (uint4*)g_qkvw_t;             n4 = DIM * DIM / 4;          break;
        case 2: src = kvw; dst = (uint4*)(g_qkvw_t + DIM*DIM); n4 = 2 * DIM * DIM / 4;      break;
        default: src = pw; dst = (uint4*)g_pw_t;               n4 = DIM * DIM / 4;          break;
    }
    for (int i = blockIdx.x * blockDim.x + threadIdx.x; i < n4; i += gridDim.x * blockDim.x) {
        float4 v = src[i];
        uint4 o;
        o.x = f2tf(v.x); o.y = f2tf(v.y); o.z = f2tf(v.z); o.w = f2tf(v.w);
        dst[i] = o;
    }
}

// ======================= TF32 tensor-core GEMM, cp.async 4-stage =======================
#define GSTAGES 4
#define STAGE_ELEMS (2 * 128 * 20)
#define GEMM_SMEM_BYTES (GSTAGES * STAGE_ELEMS * 4)   // 81920

__device__ __forceinline__ void cp_async16(uint32_t saddr, const void* gptr) {
    asm volatile("cp.async.cg.shared.global [%0], [%1], 16;" :: "r"(saddr), "l"(gptr));
}
__device__ __forceinline__ void cp_commit() {
    asm volatile("cp.async.commit_group;");
}
template<int N> __device__ __forceinline__ void cp_wait() {
    asm volatile("cp.async.wait_group %0;" :: "n"(N));
}

__device__ __forceinline__ void mma_tf32(float* d, const uint32_t* a, const uint32_t* b) {
    asm volatile(
        "mma.sync.aligned.m16n8k8.row.col.f32.tf32.tf32.f32 "
        "{%0,%1,%2,%3}, {%4,%5,%6,%7}, {%8,%9}, {%0,%1,%2,%3};"
        : "+f"(d[0]), "+f"(d[1]), "+f"(d[2]), "+f"(d[3])
        : "r"(a[0]), "r"(a[1]), "r"(a[2]), "r"(a[3]), "r"(b[0]), "r"(b[1]));
}

__device__ __forceinline__ void tf32_gemm_main(const uint32_t* __restrict__ A,
                                               const uint32_t* __restrict__ W,
                                               int K, float acc[4][4][4])
{
    extern __shared__ uint32_t dsm[];
    const int row0 = blockIdx.y * 128;
    const int col0 = blockIdx.x * 128;
    const int tid  = threadIdx.x;
    const int lane = tid & 31;
    const int warp = tid >> 5;
    const int wm = warp >> 2;
    const int wn = warp & 3;
    const int gid = lane >> 2;
    const int tig = lane & 3;

    const int lr = tid >> 1;
    const int lc = (tid & 1) * 8;

    const uint32_t* Ag = A + (size_t)(row0 + lr) * K + lc;
    const uint32_t* Wg = W + (size_t)(col0 + lr) * K + lc;

    uint32_t smem_base = (uint32_t)__cvta_generic_to_shared(dsm);
    const uint32_t a_dst = smem_base + (uint32_t)(lr * 20 + lc) * 4;
    const uint32_t b_dst = a_dst + 128 * 20 * 4;

    const int NITER = K >> 4;

#pragma unroll
    for (int i = 0; i < 4; i++)
#pragma unroll
        for (int j = 0; j < 4; j++)
#pragma unroll
            for (int r = 0; r < 4; r++) acc[i][j][r] = 0.f;

#pragma unroll
    for (int s = 0; s < GSTAGES - 1; s++) {
        uint32_t so = (uint32_t)(s * STAGE_ELEMS) * 4;
        cp_async16(a_dst + so,      Ag + s * 16);
        cp_async16(a_dst + so + 16, Ag + s * 16 + 4);
        cp_async16(b_dst + so,      Wg + s * 16);
        cp_async16(b_dst + so + 16, Wg + s * 16 + 4);
        cp_commit();
    }

    for (int it = 0; it < NITER; it++) {
        cp_wait<GSTAGES - 2>();
        __syncthreads();

        int nxt = it + GSTAGES - 1;
        if (nxt < NITER) {
            int s = nxt & (GSTAGES - 1);
            uint32_t so = (uint32_t)(s * STAGE_ELEMS) * 4;
            cp_async16(a_dst + so,      Ag + nxt * 16);
            cp_async16(a_dst + so + 16, Ag + nxt * 16 + 4);
            cp_async16(b_dst + so,      Wg + nxt * 16);
            cp_async16(b_dst + so + 16, Wg + nxt * 16 + 4);
        }
        cp_commit();

        const uint32_t* As = dsm + (it & (GSTAGES - 1)) * STAGE_ELEMS;
        const uint32_t* Bs = As + 128 * 20;

#pragma unroll
        for (int kk = 0; kk < 16; kk += 8) {
            uint32_t af[4][4], bf[4][2];
#pragma unroll
            for (int mt = 0; mt < 4; mt++) {
                int r = wm * 64 + mt * 16 + gid;
                af[mt][0] = As[r * 20 + kk + tig];
                af[mt][1] = As[(r + 8) * 20 + kk + tig];
                af[mt][2] = As[r * 20 + kk + tig + 4];
                af[mt][3] = As[(r + 8) * 20 + kk + tig + 4];
            }
#pragma unroll
            for (int nt = 0; nt < 4; nt++) {
                int cb = wn * 32 + nt * 8 + gid;
                bf[nt][0] = Bs[cb * 20 + kk + tig];
                bf[nt][1] = Bs[cb * 20 + kk + tig + 4];
            }
#pragma unroll
            for (int mt = 0; mt < 4; mt++)
#pragma unroll
                for (int nt = 0; nt < 4; nt++)
                    mma_tf32(acc[mt][nt], af[mt], bf[nt]);
        }
    }
}

// merged QKV GEMM; epilogue scatters into head-planar [b][h][n][d] arrays.
__global__ void __launch_bounds__(256, 2) gemm_qkv()
{
    float acc[4][4][4];
    tf32_gemm_main(g_xt, g_qkvw_t, DIM, acc);

    const int row0 = blockIdx.y * 128;
    const int col0 = blockIdx.x * 128;
    const int tid  = threadIdx.x;
    const int lane = tid & 31;
    const int warp = tid >> 5;
    const int wm = warp >> 2, wn = warp & 3;
    const int gid = lane >> 2, tig = lane & 3;

    const int seg = col0 >> 9;                 // 0=q,1=k,2=v
    float* P = (seg == 0) ? g_qh : (seg == 1) ? g_k : g_v;
    const int cseg = col0 & 511;

#pragma unroll
    for (int mt = 0; mt < 4; mt++) {
        int r  = row0 + wm * 64 + mt * 16 + gid;
        int bb = r / NTOK, nn = r % NTOK;
        int r8 = r + 8;
        int bb8 = r8 / NTOK, nn8 = r8 % NTOK;
#pragma unroll
        for (int nt = 0; nt < 4; nt++) {
            int c = cseg + wn * 32 + nt * 8 + 2 * tig;
            int h = c >> 6, d = c & 63;
            *(float2*)&P[(((size_t)(bb * NH + h)) * NTOK + nn) * HD + d] =
                make_float2(acc[mt][nt][0], acc[mt][nt][1]);
            *(float2*)&P[(((size_t)(bb8 * NH + h)) * NTOK + nn8) * HD + d] =
                make_float2(acc[mt][nt][2], acc[mt][nt][3]);
        }
    }
}

__global__ void __launch_bounds__(256, 2) gemm_proj(const float* __restrict__ bias,
                                                    float* __restrict__ out)
{
    float acc[4][4][4];
    tf32_gemm_main(g_attn_t, g_pw_t, DIM, acc);

    const int row0 = blockIdx.y * 128;
    const int col0 = blockIdx.x * 128;
    const int tid  = threadIdx.x;
    const int lane = tid & 31;
    const int warp = tid >> 5;
    const int wm = warp >> 2, wn = warp & 3;
    const int gid = lane >> 2, tig = lane & 3;

#pragma unroll
    for (int mt = 0; mt < 4; mt++) {
        int r = row0 + wm * 64 + mt * 16 + gid;
#pragma unroll
        for (int nt = 0; nt < 4; nt++) {
            int c = col0 + wn * 32 + nt * 8 + 2 * tig;
            float2 bb = *(const float2*)&bias[c];
            *(float2*)&out[(size_t)r * DIM + c] =
                make_float2(acc[mt][nt][0] + bb.x, acc[mt][nt][1] + bb.y);
            *(float2*)&out[(size_t)(r + 8) * DIM + c] =
                make_float2(acc[mt][nt][2] + bb.x, acc[mt][nt][3] + bb.y);
        }
    }
}

// ======================= bias precompute =======================
__device__ __forceinline__ float bilin7(const float* __restrict__ t, int i, int j)
{
    float si = (i - 1.5f) * 0.25f;
    float sj = (j - 1.5f) * 0.25f;
    float fi = floorf(si), fj = floorf(sj);
    int i0 = (int)fi, j0 = (int)fj;
    float wi = si - fi, wj = sj - fj;
    int i0c = max(0, min(6, i0)), i1c = max(0, min(6, i0 + 1));
    int j0c = max(0, min(6, j0)), j1c = max(0, min(6, j0 + 1));
    float v00 = t[i0c * 7 + j0c], v01 = t[i0c * 7 + j1c];
    float v10 = t[i1c * 7 + j0c], v11 = t[i1c * 7 + j1c];
    return (1.f - wi) * ((1.f - wj) * v00 + wj * v01)
         +        wi  * ((1.f - wj) * v10 + wj * v11);
}

__global__ void build_bias(const float* __restrict__ an_bias, const float* __restrict__ na_bias,
                           const float* __restrict__ ah_bias, const float* __restrict__ aw_bias,
                           const float* __restrict__ ha_bias, const float* __restrict__ wa_bias)
{
    int ha = blockIdx.x;
    int h = ha / DA, a = ha % DA;
    int n = threadIdx.x;
    int i = n / WW, j = n % WW;
    g_pos_bias[(size_t)ha * NTOK + n] =
        bilin7(an_bias + (size_t)ha * 49, i, j) + ah_bias[ha * HH + i] + aw_bias[ha * WW + j];
    g_agent_bias_t[(size_t)ha * NTOK + n] =
        bilin7(na_bias + (size_t)ha * 49, i, j)
        + ha_bias[(h * HH + i) * DA + a] + wa_bias[(h * WW + j) * DA + a];
}

// ======================= fused attention (pool + both attentions + dwc) =======================
// one block per (b,h), 512 threads  (R8-proven structure + dwc fused epilogue)
// dyn smem: sS[49][784] + sAg[49][64] + sAV[49][64] + sW[9][64] + sWb[64]
#define FA_SMEM_FLOATS (DA * NTOK + 2 * DA * HD + 9 * HD + HD)
#define FA_SMEM_BYTES (FA_SMEM_FLOATS * 4)   // 181312

__global__ void __launch_bounds__(512, 1) fused_attn(const float* __restrict__ dwc_w,
                                                     const float* __restrict__ dwc_b)
{
    extern __shared__ float sm[];
    float* sS  = sm;                       // [49][784]
    float* sAg = sm + DA * NTOK;           // [49][64]  (agent * scale)
    float* sAV = sAg + DA * HD;            // [49][64]
    float* sW  = sAV + DA * HD;            // [9][64]
    float* sWb = sW + 9 * HD;              // [64]
    __shared__ float sInv[DA];
    const int h = blockIdx.x, b = blockIdx.y;
    const int tid = threadIdx.x;
    const int warp = tid >> 5, lane = tid & 31;

    const float* qpl = g_qh + ((size_t)(b * NH + h)) * NTOK * HD;   // q plane [n][d]
    const float* kpl = g_k  + ((size_t)(b * NH + h)) * NTOK * HD;
    const float* vpl = g_v  + ((size_t)(b * NH + h)) * NTOK * HD;

    // ---- P0: pooled agent (4x4 avg over q image) * 1/8 scale; stage dwc weights ----
    for (int i = tid; i < DA * HD; i += 512) {
        int a = i >> 6, d = i & 63;
        int ai = a / 7, aj = a % 7;
        const float* qb = qpl + ((ai * 4) * WW + aj * 4) * HD + d;
        float s = 0.f;
#pragma unroll
        for (int di = 0; di < 4; di++)
#pragma unroll
            for (int dj = 0; dj < 4; dj++)
                s += qb[(di * WW + dj) * HD];
        sAg[i] = s * 0.0078125f;           // (1/16)*(1/8)
    }
    for (int i = tid; i < 9 * HD; i += 512)
        sW[i] = dwc_w[(h * HD + (i & 63)) * 9 + (i >> 6)];
    if (tid < HD) sWb[tid] = dwc_b[h * HD + tid];
    __syncthreads();

    // ---- P1: agent scores S[a][n] = sAg[a].k[n] + pos_bias ----
    for (int n = tid; n < NTOK; n += 512) {
        u64 kp[32];
        const ulonglong2* kr = (const ulonglong2*)(kpl + (size_t)n * HD);
#pragma unroll
        for (int i = 0; i < 16; i++) {
            ulonglong2 v = kr[i];
            kp[2 * i] = v.x; kp[2 * i + 1] = v.y;
        }
        const float* pb = g_pos_bias + (size_t)h * DA * NTOK + n;
        for (int a = 0; a < DA; a++) {
            const ulonglong2* Ar = (const ulonglong2*)&sAg[a * HD];
            u64 acc0 = 0, acc1 = 0;
#pragma unroll
            for (int i = 0; i < 16; i++) {
                ulonglong2 av = Ar[i];
                fma2(acc0, kp[2 * i], av.x);
                fma2(acc1, kp[2 * i + 1], av.y);
            }
            float2 f0 = unpack2(acc0), f1 = unpack2(acc1);
            sS[a * NTOK + n] = (f0.x + f0.y) + (f1.x + f1.y) + pb[a * NTOK];
        }
    }
    __syncthreads();

    // ---- P2: row softmax over n (warp per agent row) ----
    for (int a = warp; a < DA; a += 16) {
        float* row = sS + a * NTOK;
        float m = -1e30f;
        for (int n = lane; n < NTOK; n += 32) m = fmaxf(m, row[n]);
#pragma unroll
        for (int o = 16; o > 0; o >>= 1) m = fmaxf(m, __shfl_xor_sync(0xffffffff, m, o));
        float s = 0.f;
        for (int n = lane; n < NTOK; n += 32) { float e = __expf(row[n] - m); row[n] = e; s += e; }
#pragma unroll
        for (int o = 16; o > 0; o >>= 1) s += __shfl_xor_sync(0xffffffff, s, o);
        if (lane == 0) sInv[a] = 1.f / s;
    }
    __syncthreads();

    // ---- P3: agent_v[a][d] = (P[a] @ V)[d] * inv[a]  -> sAV ----
    {
        u64 acc[4];
#pragma unroll
        for (int i = 0; i < 4; i++) acc[i] = 0;
        const u64* vb = (const u64*)vpl + lane;
#pragma unroll 4
        for (int n = 0; n < NTOK; n++) {
            u64 vv = vb[n * 32];
#pragma unroll
            for (int i = 0; i < 4; i++) {
                int a = warp + 16 * i;
                if (a < DA) {
                    float p = sS[a * NTOK + n];
                    fma2(acc[i], pack2(p, p), vv);
                }
            }
        }
#pragma unroll
        for (int i = 0; i < 4; i++) {
            int a = warp + 16 * i;
            if (a < DA) {
                float2 f = unpack2(acc[i]);
                float inv = sInv[a];
                sAV[a * HD + lane * 2]     = f.x * inv;
                sAV[a * HD + lane * 2 + 1] = f.y * inv;
            }
        }
    }
    __syncthreads();

    // ---- P4: q attention + dwc + tf32 store; per-thread score row in sS scratch ----
    float* row = sS + tid * DA;            // 512*49 <= 49*784
    for (int n = tid; n < NTOK; n += 512) {
        u64 qp[32];
        const ulonglong2* qpt = (const ulonglong2*)(qpl + (size_t)n * HD);
#pragma unroll
        for (int i = 0; i < 16; i++) {
            ulonglong2 v = qpt[i];
            qp[2 * i] = v.x; qp[2 * i + 1] = v.y;
        }
        const float* abT = g_agent_bias_t + (size_t)h * DA * NTOK + n;
        float m = -1e30f;
        for (int a = 0; a < DA; a++) {
            const ulonglong2* Ar = (const ulonglong2*)&sAg[a * HD];
            u64 acc0 = 0, acc1 = 0;
#pragma unroll
            for (int i = 0; i < 16; i++) {
                ulonglong2 av = Ar[i];
                fma2(acc0, qp[2 * i], av.x);
                fma2(acc1, qp[2 * i + 1], av.y);
            }
            float2 f0 = unpack2(acc0), f1 = unpack2(acc1);
            float s = (f0.x + f0.y) + (f1.x + f1.y) + abT[a * NTOK];
            row[a] = s;
            m = fmaxf(m, s);
        }

        float sum = 0.f;
        for (int a = 0; a < DA; a++) { float e = __expf(row[a] - m); row[a] = e; sum += e; }
        float inv = 1.f / sum;

        u64 o[32];
#pragma unroll
        for (int i = 0; i < 32; i++) o[i] = 0;
        for (int a = 0; a < DA; a++) {
            float p = row[a] * inv;
            u64 pp = pack2(p, p);
            const ulonglong2* Vr = (const ulonglong2*)&sAV[a * HD];
#pragma unroll
            for (int i = 0; i < 16; i++) {
                ulonglong2 vv = Vr[i];
                fma2(o[2 * i], pp, vv.x);
                fma2(o[2 * i + 1], pp, vv.y);
            }
        }

        // depthwise 3x3 on v plane (fused; v rows L2-hot from P3)
        int ii = n / WW, jj = n % WW;
#pragma unroll
        for (int di = -1; di <= 1; di++) {
            int y = ii + di;
            if (y < 0 || y >= HH) continue;
#pragma unroll
            for (int dj = -1; dj <= 1; dj++) {
                int xx = jj + dj;
                if (xx < 0 || xx >= WW) continue;
                const u64* vr = (const u64*)(vpl + (size_t)(y * WW + xx) * HD);
                const u64* wr = (const u64*)(sW + ((di + 1) * 3 + (dj + 1)) * HD);
#pragma unroll
                for (int k = 0; k < 32; k++) fma2(o[k], wr[k], vr[k]);
            }
        }

        uint32_t* op = (uint32_t*)(g_attn_t + ((size_t)(b * NTOK + n)) * DIM + h * HD);
#pragma unroll
        for (int k = 0; k < 32; k++) {
            float2 f = unpack2(o[k]);
            op[2 * k]     = f2tf(f.x + sWb[2 * k]);
            op[2 * k + 1] = f2tf(f.y + sWb[2 * k + 1]);
        }
    }
}

// ======================= launch =======================
extern "C" void kernel_launch(void* const* d_in, const int* in_sizes, int n_in,
                              void* d_out, int out_size)
{
    const float* x       = (const float*)d_in[0];
    const float* q_w     = (const float*)d_in[1];
    const float* kv_w    = (const float*)d_in[2];
    const float* proj_w  = (const float*)d_in[3];
    const float* proj_b  = (const float*)d_in[4];
    const float* dwc_w   = (const float*)d_in[5];
    const float* dwc_b   = (const float*)d_in[6];
    const float* an_bias = (const float*)d_in[7];
    const float* na_bias = (const float*)d_in[8];
    const float* ah_bias = (const float*)d_in[9];
    const float* aw_bias = (const float*)d_in[10];
    const float* ha_bias = (const float*)d_in[11];
    const float* wa_bias = (const float*)d_in[12];
    float* out = (float*)d_out;

    cudaFuncSetAttribute(gemm_qkv,   cudaFuncAttributeMaxDynamicSharedMemorySize, GEMM_SMEM_BYTES);
    cudaFuncSetAttribute(gemm_proj,  cudaFuncAttributeMaxDynamicSharedMemorySize, GEMM_SMEM_BYTES);
    cudaFuncSetAttribute(fused_attn, cudaFuncAttributeMaxDynamicSharedMemorySize, FA_SMEM_BYTES);

    // 1: convert operands to tf32
    cvt_all<<<dim3(512, 4), 256>>>((const float4*)x, (const float4*)q_w,
                                   (const float4*)kv_w, (const float4*)proj_w);
    // 2: merged QKV GEMM (head-planar epilogue)
    gemm_qkv<<<dim3(3 * DIM / 128, (BATCH * NTOK) / 128), 256, GEMM_SMEM_BYTES>>>();
    // 3: bias tables
    build_bias<<<NH * DA, NTOK>>>(an_bias, na_bias, ah_bias, aw_bias, ha_bias, wa_bias);
    // 4: fused attention (+dwc)  <-- ncu-profiled slot
    fused_attn<<<dim3(NH, BATCH), 512, FA_SMEM_BYTES>>>(dwc_w, dwc_b);
    // 5: output projection
    gemm_proj<<<dim3(DIM / 128, (BATCH * NTOK) / 128), 256, GEMM_SMEM_BYTES>>>(proj_b, out);
}

// round 12
// speedup vs baseline: 1.1982x; 1.1982x over previous
#include <cuda_runtime.h>
#include <math.h>
#include <stdint.h>

// Problem constants
#define BATCH 32
#define NTOK  784
#define DIM   512
#define NH    8
#define HD    64
#define HH    28
#define WW    28
#define DA    49

typedef unsigned long long u64;

// -------- scratch (__device__ globals; no allocations allowed) --------
// head-planar activations: [b][h][n][d]
__device__ float    g_qh[BATCH * NH * NTOK * HD];
__device__ float    g_k [BATCH * NH * NTOK * HD];
__device__ float    g_v [BATCH * NH * NTOK * HD];
__device__ float    g_pos_bias[NH * DA * NTOK];        // [h,a,n]
__device__ float    g_agent_bias_t[NH * DA * NTOK];    // [h,a,n]
__device__ float    g_attn [BATCH * NTOK * DIM];       // [b][n][c] fp32 attn staging (pre-dwc)
__device__ uint32_t g_xt   [BATCH * NTOK * DIM];
__device__ uint32_t g_qkvw_t[3 * DIM * DIM];           // q_w then kv_w [1536][512]
__device__ uint32_t g_pw_t [DIM * DIM];
__device__ uint32_t g_attn_t[BATCH * NTOK * DIM];      // tf32 attn+dwc (proj input)

__device__ __forceinline__ uint32_t f2tf(float f) {
    uint32_t u;
    asm("cvt.rna.tf32.f32 %0, %1;" : "=r"(u) : "f"(f));
    return u;
}
__device__ __forceinline__ void fma2(u64& d, u64 a, u64 b) {
    asm("fma.rn.f32x2 %0, %1, %2, %0;" : "+l"(d) : "l"(a), "l"(b));
}
__device__ __forceinline__ float2 unpack2(u64 v) {
    float2 f;
    asm("mov.b64 {%0,%1}, %2;" : "=f"(f.x), "=f"(f.y) : "l"(v));
    return f;
}
__device__ __forceinline__ u64 pack2(float lo, float hi) {
    u64 r;
    asm("mov.b64 %0, {%1,%2};" : "=l"(r) : "f"(lo), "f"(hi));
    return r;
}

// ======================= fp32 -> tf32 conversion (all operands, one kernel) =======================
__global__ void cvt_all(const float4* __restrict__ x, const float4* __restrict__ qw,
                        const float4* __restrict__ kvw, const float4* __restrict__ pw)
{
    const float4* src;
    uint4* dst;
    int n4;
    switch (blockIdx.y) {
        case 0: src = x;   dst = (uint4*)g_xt;                 n4 = BATCH * NTOK * DIM / 4; break;
        case 1: src = qw;  dst = (uint4*)g_qkvw_t;             n4 = DIM * DIM / 4;          break;
        case 2: src = kvw; dst = (uint4*)(g_qkvw_t + DIM*DIM); n4 = 2 * DIM * DIM / 4;      break;
        default: src = pw; dst = (uint4*)g_pw_t;               n4 = DIM * DIM / 4;          break;
    }
    for (int i = blockIdx.x * blockDim.x + threadIdx.x; i < n4; i += gridDim.x * blockDim.x) {
        float4 v = src[i];
        uint4 o;
        o.x = f2tf(v.x); o.y = f2tf(v.y); o.z = f2tf(v.z); o.w = f2tf(v.w);
        dst[i] = o;
    }
}

// ======================= TF32 tensor-core GEMM, cp.async 4-stage =======================
#define GSTAGES 4
#define STAGE_ELEMS (2 * 128 * 20)
#define GEMM_SMEM_BYTES (GSTAGES * STAGE_ELEMS * 4)   // 81920

__device__ __forceinline__ void cp_async16(uint32_t saddr, const void* gptr) {
    asm volatile("cp.async.cg.shared.global [%0], [%1], 16;" :: "r"(saddr), "l"(gptr));
}
__device__ __forceinline__ void cp_commit() {
    asm volatile("cp.async.commit_group;");
}
template<int N> __device__ __forceinline__ void cp_wait() {
    asm volatile("cp.async.wait_group %0;" :: "n"(N));
}

__device__ __forceinline__ void mma_tf32(float* d, const uint32_t* a, const uint32_t* b) {
    asm volatile(
        "mma.sync.aligned.m16n8k8.row.col.f32.tf32.tf32.f32 "
        "{%0,%1,%2,%3}, {%4,%5,%6,%7}, {%8,%9}, {%0,%1,%2,%3};"
        : "+f"(d[0]), "+f"(d[1]), "+f"(d[2]), "+f"(d[3])
        : "r"(a[0]), "r"(a[1]), "r"(a[2]), "r"(a[3]), "r"(b[0]), "r"(b[1]));
}

__device__ __forceinline__ void tf32_gemm_main(const uint32_t* __restrict__ A,
                                               const uint32_t* __restrict__ W,
                                               int K, float acc[4][4][4])
{
    extern __shared__ uint32_t dsm[];
    const int row0 = blockIdx.y * 128;
    const int col0 = blockIdx.x * 128;
    const int tid  = threadIdx.x;
    const int lane = tid & 31;
    const int warp = tid >> 5;
    const int wm = warp >> 2;
    const int wn = warp & 3;
    const int gid = lane >> 2;
    const int tig = lane & 3;

    const int lr = tid >> 1;
    const int lc = (tid & 1) * 8;

    const uint32_t* Ag = A + (size_t)(row0 + lr) * K + lc;
    const uint32_t* Wg = W + (size_t)(col0 + lr) * K + lc;

    uint32_t smem_base = (uint32_t)__cvta_generic_to_shared(dsm);
    const uint32_t a_dst = smem_base + (uint32_t)(lr * 20 + lc) * 4;
    const uint32_t b_dst = a_dst + 128 * 20 * 4;

    const int NITER = K >> 4;

#pragma unroll
    for (int i = 0; i < 4; i++)
#pragma unroll
        for (int j = 0; j < 4; j++)
#pragma unroll
            for (int r = 0; r < 4; r++) acc[i][j][r] = 0.f;

#pragma unroll
    for (int s = 0; s < GSTAGES - 1; s++) {
        uint32_t so = (uint32_t)(s * STAGE_ELEMS) * 4;
        cp_async16(a_dst + so,      Ag + s * 16);
        cp_async16(a_dst + so + 16, Ag + s * 16 + 4);
        cp_async16(b_dst + so,      Wg + s * 16);
        cp_async16(b_dst + so + 16, Wg + s * 16 + 4);
        cp_commit();
    }

    for (int it = 0; it < NITER; it++) {
        cp_wait<GSTAGES - 2>();
        __syncthreads();

        int nxt = it + GSTAGES - 1;
        if (nxt < NITER) {
            int s = nxt & (GSTAGES - 1);
            uint32_t so = (uint32_t)(s * STAGE_ELEMS) * 4;
            cp_async16(a_dst + so,      Ag + nxt * 16);
            cp_async16(a_dst + so + 16, Ag + nxt * 16 + 4);
            cp_async16(b_dst + so,      Wg + nxt * 16);
            cp_async16(b_dst + so + 16, Wg + nxt * 16 + 4);
        }
        cp_commit();

        const uint32_t* As = dsm + (it & (GSTAGES - 1)) * STAGE_ELEMS;
        const uint32_t* Bs = As + 128 * 20;

#pragma unroll
        for (int kk = 0; kk < 16; kk += 8) {
            uint32_t af[4][4], bf[4][2];
#pragma unroll
            for (int mt = 0; mt < 4; mt++) {
                int r = wm * 64 + mt * 16 + gid;
                af[mt][0] = As[r * 20 + kk + tig];
                af[mt][1] = As[(r + 8) * 20 + kk + tig];
                af[mt][2] = As[r * 20 + kk + tig + 4];
                af[mt][3] = As[(r + 8) * 20 + kk + tig + 4];
            }
#pragma unroll
            for (int nt = 0; nt < 4; nt++) {
                int cb = wn * 32 + nt * 8 + gid;
                bf[nt][0] = Bs[cb * 20 + kk + tig];
                bf[nt][1] = Bs[cb * 20 + kk + tig + 4];
            }
#pragma unroll
            for (int mt = 0; mt < 4; mt++)
#pragma unroll
                for (int nt = 0; nt < 4; nt++)
                    mma_tf32(acc[mt][nt], af[mt], bf[nt]);
        }
    }
}

// merged QKV GEMM; epilogue scatters into head-planar [b][h][n][d] arrays.
__global__ void __launch_bounds__(256, 2) gemm_qkv()
{
    float acc[4][4][4];
    tf32_gemm_main(g_xt, g_qkvw_t, DIM, acc);

    const int row0 = blockIdx.y * 128;
    const int col0 = blockIdx.x * 128;
    const int tid  = threadIdx.x;
    const int lane = tid & 31;
    const int warp = tid >> 5;
    const int wm = warp >> 2, wn = warp & 3;
    const int gid = lane >> 2, tig = lane & 3;

    const int seg = col0 >> 9;                 // 0=q,1=k,2=v
    float* P = (seg == 0) ? g_qh : (seg == 1) ? g_k : g_v;
    const int cseg = col0 & 511;

#pragma unroll
    for (int mt = 0; mt < 4; mt++) {
        int r  = row0 + wm * 64 + mt * 16 + gid;
        int bb = r / NTOK, nn = r % NTOK;
        int r8 = r + 8;
        int bb8 = r8 / NTOK, nn8 = r8 % NTOK;
#pragma unroll
        for (int nt = 0; nt < 4; nt++) {
            int c = cseg + wn * 32 + nt * 8 + 2 * tig;
            int h = c >> 6, d = c & 63;
            *(float2*)&P[(((size_t)(bb * NH + h)) * NTOK + nn) * HD + d] =
                make_float2(acc[mt][nt][0], acc[mt][nt][1]);
            *(float2*)&P[(((size_t)(bb8 * NH + h)) * NTOK + nn8) * HD + d] =
                make_float2(acc[mt][nt][2], acc[mt][nt][3]);
        }
    }
}

__global__ void __launch_bounds__(256, 2) gemm_proj(const float* __restrict__ bias,
                                                    float* __restrict__ out)
{
    float acc[4][4][4];
    tf32_gemm_main(g_attn_t, g_pw_t, DIM, acc);

    const int row0 = blockIdx.y * 128;
    const int col0 = blockIdx.x * 128;
    const int tid  = threadIdx.x;
    const int lane = tid & 31;
    const int warp = tid >> 5;
    const int wm = warp >> 2, wn = warp & 3;
    const int gid = lane >> 2, tig = lane & 3;

#pragma unroll
    for (int mt = 0; mt < 4; mt++) {
        int r = row0 + wm * 64 + mt * 16 + gid;
#pragma unroll
        for (int nt = 0; nt < 4; nt++) {
            int c = col0 + wn * 32 + nt * 8 + 2 * tig;
            float2 bb = *(const float2*)&bias[c];
            *(float2*)&out[(size_t)r * DIM + c] =
                make_float2(acc[mt][nt][0] + bb.x, acc[mt][nt][1] + bb.y);
            *(float2*)&out[(size_t)(r + 8) * DIM + c] =
                make_float2(acc[mt][nt][2] + bb.x, acc[mt][nt][3] + bb.y);
        }
    }
}

// ======================= bias precompute =======================
__device__ __forceinline__ float bilin7(const float* __restrict__ t, int i, int j)
{
    float si = (i - 1.5f) * 0.25f;
    float sj = (j - 1.5f) * 0.25f;
    float fi = floorf(si), fj = floorf(sj);
    int i0 = (int)fi, j0 = (int)fj;
    float wi = si - fi, wj = sj - fj;
    int i0c = max(0, min(6, i0)), i1c = max(0, min(6, i0 + 1));
    int j0c = max(0, min(6, j0)), j1c = max(0, min(6, j0 + 1));
    float v00 = t[i0c * 7 + j0c], v01 = t[i0c * 7 + j1c];
    float v10 = t[i1c * 7 + j0c], v11 = t[i1c * 7 + j1c];
    return (1.f - wi) * ((1.f - wj) * v00 + wj * v01)
         +        wi  * ((1.f - wj) * v10 + wj * v11);
}

__global__ void build_bias(const float* __restrict__ an_bias, const float* __restrict__ na_bias,
                           const float* __restrict__ ah_bias, const float* __restrict__ aw_bias,
                           const float* __restrict__ ha_bias, const float* __restrict__ wa_bias)
{
    int ha = blockIdx.x;
    int h = ha / DA, a = ha % DA;
    int n = threadIdx.x;
    int i = n / WW, j = n % WW;
    g_pos_bias[(size_t)ha * NTOK + n] =
        bilin7(an_bias + (size_t)ha * 49, i, j) + ah_bias[ha * HH + i] + aw_bias[ha * WW + j];
    g_agent_bias_t[(size_t)ha * NTOK + n] =
        bilin7(na_bias + (size_t)ha * 49, i, j)
        + ha_bias[(h * HH + i) * DA + a] + wa_bias[(h * WW + j) * DA + a];
}

// ======================= fused attention (pool + agent-attn + q-attn) =======================
// one block per (b,h), 512 threads (R8 structure; agent loops unrolled x2 for LDS ILP)
// dyn smem: sS[49][784] + sAg[49][64] + sAV[49][64]
#define FA_SMEM_BYTES ((DA * NTOK + 2 * DA * HD) * 4)   // 178752

__global__ void __launch_bounds__(512, 1) fused_attn()
{
    extern __shared__ float sm[];
    float* sS  = sm;                       // [49][784]
    float* sAg = sm + DA * NTOK;           // [49][64]  (agent * scale)
    float* sAV = sAg + DA * HD;            // [49][64]
    __shared__ float sInv[DA];
    const int h = blockIdx.x, b = blockIdx.y;
    const int tid = threadIdx.x;
    const int warp = tid >> 5, lane = tid & 31;

    const float* qpl = g_qh + ((size_t)(b * NH + h)) * NTOK * HD;   // q plane [n][d]
    const float* kpl = g_k  + ((size_t)(b * NH + h)) * NTOK * HD;
    const float* vpl = g_v  + ((size_t)(b * NH + h)) * NTOK * HD;

    // ---- P0: pooled agent (4x4 avg over q image), scaled by 1/8 ----
    for (int i = tid; i < DA * HD; i += 512) {
        int a = i >> 6, d = i & 63;
        int ai = a / 7, aj = a % 7;
        const float* qb = qpl + ((ai * 4) * WW + aj * 4) * HD + d;
        float s = 0.f;
#pragma unroll
        for (int di = 0; di < 4; di++)
#pragma unroll
            for (int dj = 0; dj < 4; dj++)
                s += qb[(di * WW + dj) * HD];
        sAg[i] = s * 0.0078125f;           // (1/16)*(1/8)
    }
    __syncthreads();

    // ---- P1: agent scores S[a][n] = sAg[a].k[n] + pos_bias  (agents x2 per iter) ----
    for (int n = tid; n < NTOK; n += 512) {
        u64 kp[32];
        const ulonglong2* kr = (const ulonglong2*)(kpl + (size_t)n * HD);
#pragma unroll
        for (int i = 0; i < 16; i++) {
            ulonglong2 v = kr[i];
            kp[2 * i] = v.x; kp[2 * i + 1] = v.y;
        }
        const float* pb = g_pos_bias + (size_t)h * DA * NTOK + n;
        int a = 0;
        for (; a + 1 < DA; a += 2) {
            const ulonglong2* Ar0 = (const ulonglong2*)&sAg[a * HD];
            const ulonglong2* Ar1 = (const ulonglong2*)&sAg[(a + 1) * HD];
            u64 a00 = 0, a01 = 0, a10 = 0, a11 = 0;
#pragma unroll
            for (int i = 0; i < 16; i++) {
                ulonglong2 v0 = Ar0[i], v1 = Ar1[i];
                fma2(a00, kp[2 * i],     v0.x);
                fma2(a01, kp[2 * i + 1], v0.y);
                fma2(a10, kp[2 * i],     v1.x);
                fma2(a11, kp[2 * i + 1], v1.y);
            }
            float2 f00 = unpack2(a00), f01 = unpack2(a01);
            float2 f10 = unpack2(a10), f11 = unpack2(a11);
            sS[a * NTOK + n]       = (f00.x + f00.y) + (f01.x + f01.y) + pb[a * NTOK];
            sS[(a + 1) * NTOK + n] = (f10.x + f10.y) + (f11.x + f11.y) + pb[(a + 1) * NTOK];
        }
        {   // tail agent (a = 48)
            const ulonglong2* Ar = (const ulonglong2*)&sAg[a * HD];
            u64 acc0 = 0, acc1 = 0;
#pragma unroll
            for (int i = 0; i < 16; i++) {
                ulonglong2 av = Ar[i];
                fma2(acc0, kp[2 * i], av.x);
                fma2(acc1, kp[2 * i + 1], av.y);
            }
            float2 f0 = unpack2(acc0), f1 = unpack2(acc1);
            sS[a * NTOK + n] = (f0.x + f0.y) + (f1.x + f1.y) + pb[a * NTOK];
        }
    }
    __syncthreads();

    // ---- P2: row softmax over n (warp per agent row) ----
    for (int a = warp; a < DA; a += 16) {
        float* row = sS + a * NTOK;
        float m = -1e30f;
        for (int n = lane; n < NTOK; n += 32) m = fmaxf(m, row[n]);
#pragma unroll
        for (int o = 16; o > 0; o >>= 1) m = fmaxf(m, __shfl_xor_sync(0xffffffff, m, o));
        float s = 0.f;
        for (int n = lane; n < NTOK; n += 32) { float e = __expf(row[n] - m); row[n] = e; s += e; }
#pragma unroll
        for (int o = 16; o > 0; o >>= 1) s += __shfl_xor_sync(0xffffffff, s, o);
        if (lane == 0) sInv[a] = 1.f / s;
    }
    __syncthreads();

    // ---- P3: agent_v[a][d] = (P[a] @ V)[d] * inv[a]  -> sAV ----
    {
        u64 acc[4];
#pragma unroll
        for (int i = 0; i < 4; i++) acc[i] = 0;
        const u64* vb = (const u64*)vpl + lane;
#pragma unroll 4
        for (int n = 0; n < NTOK; n++) {
            u64 vv = vb[n * 32];
#pragma unroll
            for (int i = 0; i < 4; i++) {
                int a = warp + 16 * i;
                if (a < DA) {
                    float p = sS[a * NTOK + n];
                    fma2(acc[i], pack2(p, p), vv);
                }
            }
        }
#pragma unroll
        for (int i = 0; i < 4; i++) {
            int a = warp + 16 * i;
            if (a < DA) {
                float2 f = unpack2(acc[i]);
                float inv = sInv[a];
                sAV[a * HD + lane * 2]     = f.x * inv;
                sAV[a * HD + lane * 2 + 1] = f.y * inv;
            }
        }
    }
    __syncthreads();

    // ---- P4: q attention (agents x2 per iter); per-thread score row in sS scratch ----
    float* row = sS + tid * DA;            // 512*49 <= 49*784
    for (int n = tid; n < NTOK; n += 512) {
        u64 qp[32];
        const ulonglong2* qpt = (const ulonglong2*)(qpl + (size_t)n * HD);
#pragma unroll
        for (int i = 0; i < 16; i++) {
            ulonglong2 v = qpt[i];
            qp[2 * i] = v.x; qp[2 * i + 1] = v.y;
        }
        const float* abT = g_agent_bias_t + (size_t)h * DA * NTOK + n;
        float m = -1e30f;
        {
            int a = 0;
            for (; a + 1 < DA; a += 2) {
                const ulonglong2* Ar0 = (const ulonglong2*)&sAg[a * HD];
                const ulonglong2* Ar1 = (const ulonglong2*)&sAg[(a + 1) * HD];
                u64 a00 = 0, a01 = 0, a10 = 0, a11 = 0;
#pragma unroll
                for (int i = 0; i < 16; i++) {
                    ulonglong2 v0 = Ar0[i], v1 = Ar1[i];
                    fma2(a00, qp[2 * i],     v0.x);
                    fma2(a01, qp[2 * i + 1], v0.y);
                    fma2(a10, qp[2 * i],     v1.x);
                    fma2(a11, qp[2 * i + 1], v1.y);
                }
                float2 f00 = unpack2(a00), f01 = unpack2(a01);
                float2 f10 = unpack2(a10), f11 = unpack2(a11);
                float s0 = (f00.x + f00.y) + (f01.x + f01.y) + abT[a * NTOK];
                float s1 = (f10.x + f10.y) + (f11.x + f11.y) + abT[(a + 1) * NTOK];
                row[a] = s0; row[a + 1] = s1;
                m = fmaxf(m, fmaxf(s0, s1));
            }
            {   // tail agent (a = 48)
                const ulonglong2* Ar = (const ulonglong2*)&sAg[a * HD];
                u64 acc0 = 0, acc1 = 0;
#pragma unroll
                for (int i = 0; i < 16; i++) {
                    ulonglong2 av = Ar[i];
                    fma2(acc0, qp[2 * i], av.x);
                    fma2(acc1, qp[2 * i + 1], av.y);
                }
                float2 f0 = unpack2(acc0), f1 = unpack2(acc1);
                float s = (f0.x + f0.y) + (f1.x + f1.y) + abT[a * NTOK];
                row[a] = s;
                m = fmaxf(m, s);
            }
        }

        float sum = 0.f;
        for (int a = 0; a < DA; a++) { float e = __expf(row[a] - m); row[a] = e; sum += e; }
        float inv = 1.f / sum;

        u64 o[32];
#pragma unroll
        for (int i = 0; i < 32; i++) o[i] = 0;
        {
            int a = 0;
            for (; a + 1 < DA; a += 2) {
                float p0 = row[a] * inv, p1 = row[a + 1] * inv;
                u64 pp0 = pack2(p0, p0), pp1 = pack2(p1, p1);
                const ulonglong2* V0 = (const ulonglong2*)&sAV[a * HD];
                const ulonglong2* V1 = (const ulonglong2*)&sAV[(a + 1) * HD];
#pragma unroll
                for (int i = 0; i < 16; i++) {
                    ulonglong2 v0 = V0[i], v1 = V1[i];
                    fma2(o[2 * i],     pp0, v0.x);
                    fma2(o[2 * i + 1], pp0, v0.y);
                    fma2(o[2 * i],     pp1, v1.x);
                    fma2(o[2 * i + 1], pp1, v1.y);
                }
            }
            {   // tail agent
                float p = row[a] * inv;
                u64 pp = pack2(p, p);
                const ulonglong2* Vr = (const ulonglong2*)&sAV[a * HD];
#pragma unroll
                for (int i = 0; i < 16; i++) {
                    ulonglong2 vv = Vr[i];
                    fma2(o[2 * i], pp, vv.x);
                    fma2(o[2 * i + 1], pp, vv.y);
                }
            }
        }
        float4* op = (float4*)(g_attn + ((size_t)(b * NTOK + n)) * DIM + h * HD);
#pragma unroll
        for (int i = 0; i < 16; i++) {
            float2 lo = unpack2(o[2 * i]), hi = unpack2(o[2 * i + 1]);
            op[i] = make_float4(lo.x, lo.y, hi.x, hi.y);
        }
    }
}

// ======================= depthwise 3x3 conv on v, + attn, -> tf32 (R8-proven) =======================
__global__ void dwc_add(const float* __restrict__ w, const float* __restrict__ bias)
{
    int n = blockIdx.x, b = blockIdx.y;
    int c = threadIdx.x;
    int h = c >> 6, d = c & 63;
    int i = n / WW, j = n % WW;
    const float* vpl = g_v + ((size_t)(b * NH + h)) * NTOK * HD + d;
    float acc = bias[c];
#pragma unroll
    for (int di = 0; di < 3; di++) {
        int ii = i + di - 1;
        if (ii < 0 || ii > HH - 1) continue;
#pragma unroll
        for (int dj = 0; dj < 3; dj++) {
            int jj = j + dj - 1;
            if (jj < 0 || jj > WW - 1) continue;
            acc = fmaf(w[c * 9 + di * 3 + dj], vpl[(size_t)(ii * WW + jj) * HD], acc);
        }
    }
    size_t idx = ((size_t)(b * NTOK + n)) * DIM + c;
    g_attn_t[idx] = f2tf(g_attn[idx] + acc);
}

// ======================= launch =======================
extern "C" void kernel_launch(void* const* d_in, const int* in_sizes, int n_in,
                              void* d_out, int out_size)
{
    const float* x       = (const float*)d_in[0];
    const float* q_w     = (const float*)d_in[1];
    const float* kv_w    = (const float*)d_in[2];
    const float* proj_w  = (const float*)d_in[3];
    const float* proj_b  = (const float*)d_in[4];
    const float* dwc_w   = (const float*)d_in[5];
    const float* dwc_b   = (const float*)d_in[6];
    const float* an_bias = (const float*)d_in[7];
    const float* na_bias = (const float*)d_in[8];
    const float* ah_bias = (const float*)d_in[9];
    const float* aw_bias = (const float*)d_in[10];
    const float* ha_bias = (const float*)d_in[11];
    const float* wa_bias = (const float*)d_in[12];
    float* out = (float*)d_out;

    cudaFuncSetAttribute(gemm_qkv,   cudaFuncAttributeMaxDynamicSharedMemorySize, GEMM_SMEM_BYTES);
    cudaFuncSetAttribute(gemm_proj,  cudaFuncAttributeMaxDynamicSharedMemorySize, GEMM_SMEM_BYTES);
    cudaFuncSetAttribute(fused_attn, cudaFuncAttributeMaxDynamicSharedMemorySize, FA_SMEM_BYTES);

    // 1: convert operands to tf32
    cvt_all<<<dim3(512, 4), 256>>>((const float4*)x, (const float4*)q_w,
                                   (const float4*)kv_w, (const float4*)proj_w);
    // 2: merged QKV GEMM (head-planar epilogue)
    gemm_qkv<<<dim3(3 * DIM / 128, (BATCH * NTOK) / 128), 256, GEMM_SMEM_BYTES>>>();
    // 3: bias tables
    build_bias<<<NH * DA, NTOK>>>(an_bias, na_bias, ah_bias, aw_bias, ha_bias, wa_bias);
    // 4: fused attention  <-- ncu-profiled slot
    fused_attn<<<dim3(NH, BATCH), 512, FA_SMEM_BYTES>>>();
    // 5: depthwise conv + add + tf32 convert (coalesced, proven)
    dwc_add<<<dim3(NTOK, BATCH), DIM>>>(dwc_w, dwc_b);
    // 6: output projection
    gemm_proj<<<dim3(DIM / 128, (BATCH * NTOK) / 128), 256, GEMM_SMEM_BYTES>>>(proj_b, out);
}

// round 13
// speedup vs baseline: 1.2303x; 1.0268x over previous
#include <cuda_runtime.h>
#include <math.h>
#include <stdint.h>

// Problem constants
#define BATCH 32
#define NTOK  784
#define DIM   512
#define NH    8
#define HD    64
#define HH    28
#define WW    28
#define DA    49

typedef unsigned long long u64;

// -------- scratch (__device__ globals; no allocations allowed) --------
// head-planar activations: [b][h][n][d]
__device__ float    g_qh[BATCH * NH * NTOK * HD];
__device__ float    g_k [BATCH * NH * NTOK * HD];
__device__ float    g_v [BATCH * NH * NTOK * HD];
__device__ float    g_ag [BATCH * NH * DA * HD];       // scaled pooled agents [b][h][a][d]
__device__ float    g_avT[BATCH * NH * HD * DA];       // agent_v transposed [b][h][d][a]
__device__ float    g_pos_bias[NH * DA * NTOK];        // [h,a,n]
__device__ float    g_agent_bias[NH * NTOK * DA];      // [h,n,a]
__device__ float    g_attn [BATCH * NTOK * DIM];       // [b][n][c] fp32 attn staging (pre-dwc)
__device__ uint32_t g_xt   [BATCH * NTOK * DIM];
__device__ uint32_t g_qkvw_t[3 * DIM * DIM];           // q_w then kv_w [1536][512]
__device__ uint32_t g_pw_t [DIM * DIM];
__device__ uint32_t g_attn_t[BATCH * NTOK * DIM];      // tf32 attn+dwc (proj input)

__device__ __forceinline__ uint32_t f2tf(float f) {
    uint32_t u;
    asm("cvt.rna.tf32.f32 %0, %1;" : "=r"(u) : "f"(f));
    return u;
}
__device__ __forceinline__ void fma2(u64& d, u64 a, u64 b) {
    asm("fma.rn.f32x2 %0, %1, %2, %0;" : "+l"(d) : "l"(a), "l"(b));
}
__device__ __forceinline__ float2 unpack2(u64 v) {
    float2 f;
    asm("mov.b64 {%0,%1}, %2;" : "=f"(f.x), "=f"(f.y) : "l"(v));
    return f;
}
__device__ __forceinline__ u64 pack2(float lo, float hi) {
    u64 r;
    asm("mov.b64 %0, {%1,%2};" : "=l"(r) : "f"(lo), "f"(hi));
    return r;
}

// ======================= fp32 -> tf32 conversion (all operands, one kernel) =======================
__global__ void cvt_all(const float4* __restrict__ x, const float4* __restrict__ qw,
                        const float4* __restrict__ kvw, const float4* __restrict__ pw)
{
    const float4* src;
    uint4* dst;
    int n4;
    switch (blockIdx.y) {
        case 0: src = x;   dst = (uint4*)g_xt;                 n4 = BATCH * NTOK * DIM / 4; break;
        case 1: src = qw;  dst = (uint4*)g_qkvw_t;             n4 = DIM * DIM / 4;          break;
        case 2: src = kvw; dst = (uint4*)(g_qkvw_t + DIM*DIM); n4 = 2 * DIM * DIM / 4;      break;
        default: src = pw; dst = (uint4*)g_pw_t;               n4 = DIM * DIM / 4;          break;
    }
    for (int i = blockIdx.x * blockDim.x + threadIdx.x; i < n4; i += gridDim.x * blockDim.x) {
        float4 v = src[i];
        uint4 o;
        o.x = f2tf(v.x); o.y = f2tf(v.y); o.z = f2tf(v.z); o.w = f2tf(v.w);
        dst[i] = o;
    }
}

// ======================= TF32 tensor-core GEMM, cp.async 4-stage =======================
#define GSTAGES 4
#define STAGE_ELEMS (2 * 128 * 20)
#define GEMM_SMEM_BYTES (GSTAGES * STAGE_ELEMS * 4)   // 81920

__device__ __forceinline__ void cp_async16(uint32_t saddr, const void* gptr) {
    asm volatile("cp.async.cg.shared.global [%0], [%1], 16;" :: "r"(saddr), "l"(gptr));
}
__device__ __forceinline__ void cp_commit() {
    asm volatile("cp.async.commit_group;");
}
template<int N> __device__ __forceinline__ void cp_wait() {
    asm volatile("cp.async.wait_group %0;" :: "n"(N));
}

__device__ __forceinline__ void mma_tf32(float* d, const uint32_t* a, const uint32_t* b) {
    asm volatile(
        "mma.sync.aligned.m16n8k8.row.col.f32.tf32.tf32.f32 "
        "{%0,%1,%2,%3}, {%4,%5,%6,%7}, {%8,%9}, {%0,%1,%2,%3};"
        : "+f"(d[0]), "+f"(d[1]), "+f"(d[2]), "+f"(d[3])
        : "r"(a[0]), "r"(a[1]), "r"(a[2]), "r"(a[3]), "r"(b[0]), "r"(b[1]));
}

__device__ __forceinline__ void tf32_gemm_main(const uint32_t* __restrict__ A,
                                               const uint32_t* __restrict__ W,
                                               int K, float acc[4][4][4])
{
    extern __shared__ uint32_t dsm[];
    const int row0 = blockIdx.y * 128;
    const int col0 = blockIdx.x * 128;
    const int tid  = threadIdx.x;
    const int lane = tid & 31;
    const int warp = tid >> 5;
    const int wm = warp >> 2;
    const int wn = warp & 3;
    const int gid = lane >> 2;
    const int tig = lane & 3;

    const int lr = tid >> 1;
    const int lc = (tid & 1) * 8;

    const uint32_t* Ag = A + (size_t)(row0 + lr) * K + lc;
    const uint32_t* Wg = W + (size_t)(col0 + lr) * K + lc;

    uint32_t smem_base = (uint32_t)__cvta_generic_to_shared(dsm);
    const uint32_t a_dst = smem_base + (uint32_t)(lr * 20 + lc) * 4;
    const uint32_t b_dst = a_dst + 128 * 20 * 4;

    const int NITER = K >> 4;

#pragma unroll
    for (int i = 0; i < 4; i++)
#pragma unroll
        for (int j = 0; j < 4; j++)
#pragma unroll
            for (int r = 0; r < 4; r++) acc[i][j][r] = 0.f;

#pragma unroll
    for (int s = 0; s < GSTAGES - 1; s++) {
        uint32_t so = (uint32_t)(s * STAGE_ELEMS) * 4;
        cp_async16(a_dst + so,      Ag + s * 16);
        cp_async16(a_dst + so + 16, Ag + s * 16 + 4);
        cp_async16(b_dst + so,      Wg + s * 16);
        cp_async16(b_dst + so + 16, Wg + s * 16 + 4);
        cp_commit();
    }

    for (int it = 0; it < NITER; it++) {
        cp_wait<GSTAGES - 2>();
        __syncthreads();

        int nxt = it + GSTAGES - 1;
        if (nxt < NITER) {
            int s = nxt & (GSTAGES - 1);
            uint32_t so = (uint32_t)(s * STAGE_ELEMS) * 4;
            cp_async16(a_dst + so,      Ag + nxt * 16);
            cp_async16(a_dst + so + 16, Ag + nxt * 16 + 4);
            cp_async16(b_dst + so,      Wg + nxt * 16);
            cp_async16(b_dst + so + 16, Wg + nxt * 16 + 4);
        }
        cp_commit();

        const uint32_t* As = dsm + (it & (GSTAGES - 1)) * STAGE_ELEMS;
        const uint32_t* Bs = As + 128 * 20;

#pragma unroll
        for (int kk = 0; kk < 16; kk += 8) {
            uint32_t af[4][4], bf[4][2];
#pragma unroll
            for (int mt = 0; mt < 4; mt++) {
                int r = wm * 64 + mt * 16 + gid;
                af[mt][0] = As[r * 20 + kk + tig];
                af[mt][1] = As[(r + 8) * 20 + kk + tig];
                af[mt][2] = As[r * 20 + kk + tig + 4];
                af[mt][3] = As[(r + 8) * 20 + kk + tig + 4];
            }
#pragma unroll
            for (int nt = 0; nt < 4; nt++) {
                int cb = wn * 32 + nt * 8 + gid;
                bf[nt][0] = Bs[cb * 20 + kk + tig];
                bf[nt][1] = Bs[cb * 20 + kk + tig + 4];
            }
#pragma unroll
            for (int mt = 0; mt < 4; mt++)
#pragma unroll
                for (int nt = 0; nt < 4; nt++)
                    mma_tf32(acc[mt][nt], af[mt], bf[nt]);
        }
    }
}

// merged QKV GEMM; epilogue scatters into head-planar [b][h][n][d] arrays.
__global__ void __launch_bounds__(256, 2) gemm_qkv()
{
    float acc[4][4][4];
    tf32_gemm_main(g_xt, g_qkvw_t, DIM, acc);

    const int row0 = blockIdx.y * 128;
    const int col0 = blockIdx.x * 128;
    const int tid  = threadIdx.x;
    const int lane = tid & 31;
    const int warp = tid >> 5;
    const int wm = warp >> 2, wn = warp & 3;
    const int gid = lane >> 2, tig = lane & 3;

    const int seg = col0 >> 9;                 // 0=q,1=k,2=v
    float* P = (seg == 0) ? g_qh : (seg == 1) ? g_k : g_v;
    const int cseg = col0 & 511;

#pragma unroll
    for (int mt = 0; mt < 4; mt++) {
        int r  = row0 + wm * 64 + mt * 16 + gid;
        int bb = r / NTOK, nn = r % NTOK;
        int r8 = r + 8;
        int bb8 = r8 / NTOK, nn8 = r8 % NTOK;
#pragma unroll
        for (int nt = 0; nt < 4; nt++) {
            int c = cseg + wn * 32 + nt * 8 + 2 * tig;
            int h = c >> 6, d = c & 63;
            *(float2*)&P[(((size_t)(bb * NH + h)) * NTOK + nn) * HD + d] =
                make_float2(acc[mt][nt][0], acc[mt][nt][1]);
            *(float2*)&P[(((size_t)(bb8 * NH + h)) * NTOK + nn8) * HD + d] =
                make_float2(acc[mt][nt][2], acc[mt][nt][3]);
        }
    }
}

__global__ void __launch_bounds__(256, 2) gemm_proj(const float* __restrict__ bias,
                                                    float* __restrict__ out)
{
    float acc[4][4][4];
    tf32_gemm_main(g_attn_t, g_pw_t, DIM, acc);

    const int row0 = blockIdx.y * 128;
    const int col0 = blockIdx.x * 128;
    const int tid  = threadIdx.x;
    const int lane = tid & 31;
    const int warp = tid >> 5;
    const int wm = warp >> 2, wn = warp & 3;
    const int gid = lane >> 2, tig = lane & 3;

#pragma unroll
    for (int mt = 0; mt < 4; mt++) {
        int r = row0 + wm * 64 + mt * 16 + gid;
#pragma unroll
        for (int nt = 0; nt < 4; nt++) {
            int c = col0 + wn * 32 + nt * 8 + 2 * tig;
            float2 bb = *(const float2*)&bias[c];
            *(float2*)&out[(size_t)r * DIM + c] =
                make_float2(acc[mt][nt][0] + bb.x, acc[mt][nt][1] + bb.y);
            *(float2*)&out[(size_t)(r + 8) * DIM + c] =
                make_float2(acc[mt][nt][2] + bb.x, acc[mt][nt][3] + bb.y);
        }
    }
}

// ======================= bias precompute =======================
__device__ __forceinline__ float bilin7(const float* __restrict__ t, int i, int j)
{
    float si = (i - 1.5f) * 0.25f;
    float sj = (j - 1.5f) * 0.25f;
    float fi = floorf(si), fj = floorf(sj);
    int i0 = (int)fi, j0 = (int)fj;
    float wi = si - fi, wj = sj - fj;
    int i0c = max(0, min(6, i0)), i1c = max(0, min(6, i0 + 1));
    int j0c = max(0, min(6, j0)), j1c = max(0, min(6, j0 + 1));
    float v00 = t[i0c * 7 + j0c], v01 = t[i0c * 7 + j1c];
    float v10 = t[i1c * 7 + j0c], v11 = t[i1c * 7 + j1c];
    return (1.f - wi) * ((1.f - wj) * v00 + wj * v01)
         +        wi  * ((1.f - wj) * v10 + wj * v11);
}

__global__ void build_bias(const float* __restrict__ an_bias, const float* __restrict__ na_bias,
                           const float* __restrict__ ah_bias, const float* __restrict__ aw_bias,
                           const float* __restrict__ ha_bias, const float* __restrict__ wa_bias)
{
    int ha = blockIdx.x;
    int h = ha / DA, a = ha % DA;
    int n = threadIdx.x;
    int i = n / WW, j = n % WW;
    g_pos_bias[(size_t)ha * NTOK + n] =
        bilin7(an_bias + (size_t)ha * 49, i, j) + ah_bias[ha * HH + i] + aw_bias[ha * WW + j];
    g_agent_bias[((size_t)h * NTOK + n) * DA + a] =
        bilin7(na_bias + (size_t)ha * 49, i, j)
        + ha_bias[(h * HH + i) * DA + a] + wa_bias[(h * WW + j) * DA + a];
}

// ======================= agent attention (pool + agent scores + softmax + AV) =======================
// one block per (b,h), 512 threads; writes g_ag (scaled agents) and g_avT ([d][a])
// dyn smem: sS[49][784] + sAg[49][64]
#define AA_SMEM_BYTES ((DA * NTOK + DA * HD) * 4)   // 166208

__global__ void __launch_bounds__(512, 1) agent_attn()
{
    extern __shared__ float sm[];
    float* sS  = sm;                       // [49][784]
    float* sAg = sm + DA * NTOK;           // [49][64]  (agent * scale)
    __shared__ float sInv[DA];
    const int h = blockIdx.x, b = blockIdx.y;
    const int tid = threadIdx.x;
    const int warp = tid >> 5, lane = tid & 31;

    const float* qpl = g_qh + ((size_t)(b * NH + h)) * NTOK * HD;
    const float* kpl = g_k  + ((size_t)(b * NH + h)) * NTOK * HD;
    const float* vpl = g_v  + ((size_t)(b * NH + h)) * NTOK * HD;

    // ---- P0: pooled agent (4x4 avg over q image), scaled by 1/8 -> sAg + g_ag ----
    for (int i = tid; i < DA * HD; i += 512) {
        int a = i >> 6, d = i & 63;
        int ai = a / 7, aj = a % 7;
        const float* qb = qpl + ((ai * 4) * WW + aj * 4) * HD + d;
        float s = 0.f;
#pragma unroll
        for (int di = 0; di < 4; di++)
#pragma unroll
            for (int dj = 0; dj < 4; dj++)
                s += qb[(di * WW + dj) * HD];
        float v = s * 0.0078125f;          // (1/16)*(1/8)
        sAg[i] = v;
        g_ag[((size_t)(b * NH + h)) * DA * HD + i] = v;
    }
    __syncthreads();

    // ---- P1: agent scores S[a][n] = sAg[a].k[n] + pos_bias  (agents x2 per iter) ----
    for (int n = tid; n < NTOK; n += 512) {
        u64 kp[32];
        const ulonglong2* kr = (const ulonglong2*)(kpl + (size_t)n * HD);
#pragma unroll
        for (int i = 0; i < 16; i++) {
            ulonglong2 v = kr[i];
            kp[2 * i] = v.x; kp[2 * i + 1] = v.y;
        }
        const float* pb = g_pos_bias + (size_t)h * DA * NTOK + n;
        int a = 0;
        for (; a + 1 < DA; a += 2) {
            const ulonglong2* Ar0 = (const ulonglong2*)&sAg[a * HD];
            const ulonglong2* Ar1 = (const ulonglong2*)&sAg[(a + 1) * HD];
            u64 a00 = 0, a01 = 0, a10 = 0, a11 = 0;
#pragma unroll
            for (int i = 0; i < 16; i++) {
                ulonglong2 v0 = Ar0[i], v1 = Ar1[i];
                fma2(a00, kp[2 * i],     v0.x);
                fma2(a01, kp[2 * i + 1], v0.y);
                fma2(a10, kp[2 * i],     v1.x);
                fma2(a11, kp[2 * i + 1], v1.y);
            }
            float2 f00 = unpack2(a00), f01 = unpack2(a01);
            float2 f10 = unpack2(a10), f11 = unpack2(a11);
            sS[a * NTOK + n]       = (f00.x + f00.y) + (f01.x + f01.y) + pb[a * NTOK];
            sS[(a + 1) * NTOK + n] = (f10.x + f10.y) + (f11.x + f11.y) + pb[(a + 1) * NTOK];
        }
        {   // tail agent (a = 48)
            const ulonglong2* Ar = (const ulonglong2*)&sAg[a * HD];
            u64 acc0 = 0, acc1 = 0;
#pragma unroll
            for (int i = 0; i < 16; i++) {
                ulonglong2 av = Ar[i];
                fma2(acc0, kp[2 * i], av.x);
                fma2(acc1, kp[2 * i + 1], av.y);
            }
            float2 f0 = unpack2(acc0), f1 = unpack2(acc1);
            sS[a * NTOK + n] = (f0.x + f0.y) + (f1.x + f1.y) + pb[a * NTOK];
        }
    }
    __syncthreads();

    // ---- P2: row softmax over n (warp per agent row) ----
    for (int a = warp; a < DA; a += 16) {
        float* row = sS + a * NTOK;
        float m = -1e30f;
        for (int n = lane; n < NTOK; n += 32) m = fmaxf(m, row[n]);
#pragma unroll
        for (int o = 16; o > 0; o >>= 1) m = fmaxf(m, __shfl_xor_sync(0xffffffff, m, o));
        float s = 0.f;
        for (int n = lane; n < NTOK; n += 32) { float e = __expf(row[n] - m); row[n] = e; s += e; }
#pragma unroll
        for (int o = 16; o > 0; o >>= 1) s += __shfl_xor_sync(0xffffffff, s, o);
        if (lane == 0) sInv[a] = 1.f / s;
    }
    __syncthreads();

    // ---- P3: agent_v[a][d] -> g_avT [d][a] (transposed for q-attn mma B operand) ----
    {
        u64 acc[4];
#pragma unroll
        for (int i = 0; i < 4; i++) acc[i] = 0;
        const u64* vb = (const u64*)vpl + lane;
#pragma unroll 4
        for (int n = 0; n < NTOK; n++) {
            u64 vv = vb[n * 32];
#pragma unroll
            for (int i = 0; i < 4; i++) {
                int a = warp + 16 * i;
                if (a < DA) {
                    float p = sS[a * NTOK + n];
                    fma2(acc[i], pack2(p, p), vv);
                }
            }
        }
        float* avT = g_avT + ((size_t)(b * NH + h)) * HD * DA;
#pragma unroll
        for (int i = 0; i < 4; i++) {
            int a = warp + 16 * i;
            if (a < DA) {
                float2 f = unpack2(acc[i]);
                float inv = sInv[a];
                avT[(2 * lane) * DA + a]     = f.x * inv;
                avT[(2 * lane + 1) * DA + a] = f.y * inv;
            }
        }
    }
}

// ======================= q attention via tensor cores =======================
// grid (7 tiles of 112 tokens, NH, BATCH), 256 threads = 8 warps (warps 0-6 do mma).
// smem floats: sQ[112][68] | sAg[56][68] | sAvT[64][60] | sS[112][60] | sInv[112]
#define QT_SQ   0
#define QT_SAG  (112 * 68)                         // 7616
#define QT_SAVT (QT_SAG + 56 * 68)                 // 11424
#define QT_SS   (QT_SAVT + 64 * 60)                // 15264
#define QT_SINV (QT_SS + 112 * 60)                 // 21984
#define QT_SMEM_FLOATS (QT_SINV + 112)             // 22096
#define QT_SMEM_BYTES (QT_SMEM_FLOATS * 4)         // 88384

__global__ void __launch_bounds__(256, 2) q_attn_mma()
{
    extern __shared__ float sm[];
    const int tile = blockIdx.x, h = blockIdx.y, b = blockIdx.z;
    const int n0 = tile * 112;
    const int tid = threadIdx.x;
    const int lane = tid & 31, warp = tid >> 5;
    const int gid = lane >> 2, tig = lane & 3;

    const float* qpl = g_qh + ((size_t)(b * NH + h)) * NTOK * HD;
    const float* agp = g_ag + ((size_t)(b * NH + h)) * DA * HD;
    const float* avT = g_avT + ((size_t)(b * NH + h)) * HD * DA;

    uint32_t smem_base = (uint32_t)__cvta_generic_to_shared(sm);

    // ---- stage: Q tile + Ag via cp.async; AvT + bias + pads via scalar ----
    for (int i = tid; i < 112 * 16; i += 256) {
        int r = i >> 4, c = i & 15;
        cp_async16(smem_base + (uint32_t)(QT_SQ + r * 68 + c * 4) * 4,
                   qpl + (size_t)(n0 + r) * HD + c * 4);
    }
    for (int i = tid; i < DA * 16; i += 256) {
        int r = i >> 4, c = i & 15;
        cp_async16(smem_base + (uint32_t)(QT_SAG + r * 68 + c * 4) * 4,
                   agp + (size_t)r * HD + c * 4);
    }
    cp_commit();
    // zero Ag pad rows 49..55
    for (int i = tid; i < 7 * 68; i += 256)
        sm[QT_SAG + (DA + i / 68) * 68 + (i % 68)] = 0.f;
    // AvT rows [d][a], pad cols 49..55 with 0
    for (int i = tid; i < 64 * 56; i += 256) {
        int r = i / 56, c = i % 56;
        sm[QT_SAVT + r * 60 + c] = (c < DA) ? avT[r * DA + c] : 0.f;
    }
    // sS init = agent_bias [h][n][a] (cols 49..55 = 0)
    {
        const float* abp = g_agent_bias + ((size_t)h * NTOK + n0) * DA;
        for (int i = tid; i < 112 * 56; i += 256) {
            int r = i / 56, c = i % 56;
            sm[QT_SS + r * 60 + c] = (c < DA) ? abp[r * DA + c] : 0.f;
        }
    }
    cp_wait<0>();
    __syncthreads();

    // ---- phase A: sS += Q . Ag^T  (M=112, N=56, K=64) ----
    if (warp < 7) {
        const int m0 = warp * 16;
        uint32_t af[8][4];
#pragma unroll
        for (int c = 0; c < 8; c++) {
            const float* r0 = sm + QT_SQ + (m0 + gid) * 68 + 8 * c + tig;
            const float* r1 = r0 + 8 * 68;
            af[c][0] = f2tf(r0[0]);
            af[c][1] = f2tf(r1[0]);
            af[c][2] = f2tf(r0[4]);
            af[c][3] = f2tf(r1[4]);
        }
#pragma unroll
        for (int j = 0; j < 7; j++) {
            float acc[4] = {0.f, 0.f, 0.f, 0.f};
#pragma unroll
            for (int c = 0; c < 8; c++) {
                uint32_t bf[2];
                const float* br = sm + QT_SAG + (8 * j + gid) * 68 + 8 * c + tig;
                bf[0] = f2tf(br[0]);
                bf[1] = f2tf(br[4]);
                mma_tf32(acc, af[c], bf);
            }
            int col = 8 * j + 2 * tig;
            float* s0 = sm + QT_SS + (m0 + gid) * 60 + col;
            float* s1 = s0 + 8 * 60;
            s0[0] += acc[0]; s0[1] += acc[1];
            s1[0] += acc[2]; s1[1] += acc[3];
        }
    }
    __syncthreads();

    // ---- phase B: per-token softmax over agents ----
    if (tid < 112) {
        float* row = sm + QT_SS + tid * 60;
        float m = -1e30f;
        for (int a = 0; a < DA; a++) m = fmaxf(m, row[a]);
        float s = 0.f;
        for (int a = 0; a < DA; a++) { float e = __expf(row[a] - m); row[a] = e; s += e; }
#pragma unroll
        for (int a = DA; a < 56; a++) row[a] = 0.f;
        sm[QT_SINV + tid] = 1.f / s;
    }
    __syncthreads();

    // ---- phase C: O = P . AvT^T  (M=112, N=64, K=56), scale rows by 1/sum ----
    if (warp < 7) {
        const int m0 = warp * 16;
        uint32_t af[7][4];
#pragma unroll
        for (int c = 0; c < 7; c++) {
            const float* r0 = sm + QT_SS + (m0 + gid) * 60 + 8 * c + tig;
            const float* r1 = r0 + 8 * 60;
            af[c][0] = f2tf(r0[0]);
            af[c][1] = f2tf(r1[0]);
            af[c][2] = f2tf(r0[4]);
            af[c][3] = f2tf(r1[4]);
        }
        float inv0 = sm[QT_SINV + m0 + gid];
        float inv8 = sm[QT_SINV + m0 + gid + 8];
        float* orow0 = g_attn + ((size_t)(b * NTOK + n0 + m0 + gid)) * DIM + h * HD;
        float* orow8 = orow0 + (size_t)8 * DIM;
#pragma unroll
        for (int j = 0; j < 8; j++) {
            float acc[4] = {0.f, 0.f, 0.f, 0.f};
#pragma unroll
            for (int c = 0; c < 7; c++) {
                uint32_t bf[2];
                const float* br = sm + QT_SAVT + (8 * j + gid) * 60 + 8 * c + tig;
                bf[0] = f2tf(br[0]);
                bf[1] = f2tf(br[4]);
                mma_tf32(acc, af[c], bf);
            }
            int col = 8 * j + 2 * tig;
            *(float2*)&orow0[col] = make_float2(acc[0] * inv0, acc[1] * inv0);
            *(float2*)&orow8[col] = make_float2(acc[2] * inv8, acc[3] * inv8);
        }
    }
}

// ======================= depthwise 3x3 conv on v, + attn, -> tf32 =======================
__global__ void dwc_add(const float* __restrict__ w, const float* __restrict__ bias)
{
    int n = blockIdx.x, b = blockIdx.y;
    int c = threadIdx.x;
    int h = c >> 6, d = c & 63;
    int i = n / WW, j = n % WW;
    const float* vpl = g_v + ((size_t)(b * NH + h)) * NTOK * HD + d;
    float acc = bias[c];
#pragma unroll
    for (int di = 0; di < 3; di++) {
        int ii = i + di - 1;
        if (ii < 0 || ii > HH - 1) continue;
#pragma unroll
        for (int dj = 0; dj < 3; dj++) {
            int jj = j + dj - 1;
            if (jj < 0 || jj > WW - 1) continue;
            acc = fmaf(w[c * 9 + di * 3 + dj], vpl[(size_t)(ii * WW + jj) * HD], acc);
        }
    }
    size_t idx = ((size_t)(b * NTOK + n)) * DIM + c;
    g_attn_t[idx] = f2tf(g_attn[idx] + acc);
}

// ======================= launch =======================
extern "C" void kernel_launch(void* const* d_in, const int* in_sizes, int n_in,
                              void* d_out, int out_size)
{
    const float* x       = (const float*)d_in[0];
    const float* q_w     = (const float*)d_in[1];
    const float* kv_w    = (const float*)d_in[2];
    const float* proj_w  = (const float*)d_in[3];
    const float* proj_b  = (const float*)d_in[4];
    const float* dwc_w   = (const float*)d_in[5];
    const float* dwc_b   = (const float*)d_in[6];
    const float* an_bias = (const float*)d_in[7];
    const float* na_bias = (const float*)d_in[8];
    const float* ah_bias = (const float*)d_in[9];
    const float* aw_bias = (const float*)d_in[10];
    const float* ha_bias = (const float*)d_in[11];
    const float* wa_bias = (const float*)d_in[12];
    float* out = (float*)d_out;

    cudaFuncSetAttribute(gemm_qkv,   cudaFuncAttributeMaxDynamicSharedMemorySize, GEMM_SMEM_BYTES);
    cudaFuncSetAttribute(gemm_proj,  cudaFuncAttributeMaxDynamicSharedMemorySize, GEMM_SMEM_BYTES);
    cudaFuncSetAttribute(agent_attn, cudaFuncAttributeMaxDynamicSharedMemorySize, AA_SMEM_BYTES);
    cudaFuncSetAttribute(q_attn_mma, cudaFuncAttributeMaxDynamicSharedMemorySize, QT_SMEM_BYTES);

    // 1: convert operands to tf32
    cvt_all<<<dim3(512, 4), 256>>>((const float4*)x, (const float4*)q_w,
                                   (const float4*)kv_w, (const float4*)proj_w);
    // 2: merged QKV GEMM (head-planar epilogue)
    gemm_qkv<<<dim3(3 * DIM / 128, (BATCH * NTOK) / 128), 256, GEMM_SMEM_BYTES>>>();
    // 3: bias tables
    build_bias<<<NH * DA, NTOK>>>(an_bias, na_bias, ah_bias, aw_bias, ha_bias, wa_bias);
    // 4: agent attention (pool + scores + softmax + AV)  <-- ncu-profiled slot
    agent_attn<<<dim3(NH, BATCH), 512, AA_SMEM_BYTES>>>();
    // 5: q attention via tensor cores
    q_attn_mma<<<dim3(7, NH, BATCH), 256, QT_SMEM_BYTES>>>();
    // 6: depthwise conv + add + tf32 convert
    dwc_add<<<dim3(NTOK, BATCH), DIM>>>(dwc_w, dwc_b);
    // 7: output projection
    gemm_proj<<<dim3(DIM / 128, (BATCH * NTOK) / 128), 256, GEMM_SMEM_BYTES>>>(proj_b, out);
}

// round 14
// speedup vs baseline: 1.2670x; 1.0298x over previous
#include <cuda_runtime.h>
#include <math.h>
#include <stdint.h>

// Problem constants
#define BATCH 32
#define NTOK  784
#define DIM   512
#define NH    8
#define HD    64
#define HH    28
#define WW    28
#define DA    49

typedef unsigned long long u64;

// -------- scratch (__device__ globals; no allocations allowed) --------
// head-planar activations: [b][h][n][d]
__device__ float    g_qh[BATCH * NH * NTOK * HD];
__device__ float    g_k [BATCH * NH * NTOK * HD];
__device__ float    g_v [BATCH * NH * NTOK * HD];
__device__ float    g_ag [BATCH * NH * DA * HD];       // scaled pooled agents [b][h][a][d] (tf32-rounded)
__device__ float    g_avT[BATCH * NH * HD * DA];       // agent_v transposed [b][h][d][a]
__device__ float    g_pos_bias[NH * DA * NTOK];        // [h,a,n]
__device__ float    g_agent_bias[NH * NTOK * DA];      // [h,n,a]
__device__ float    g_attn [BATCH * NTOK * DIM];       // [b][n][c] fp32 attn staging (pre-dwc)
__device__ uint32_t g_xt   [BATCH * NTOK * DIM];
__device__ uint32_t g_qkvw_t[3 * DIM * DIM];           // q_w then kv_w [1536][512]
__device__ uint32_t g_pw_t [DIM * DIM];
__device__ uint32_t g_attn_t[BATCH * NTOK * DIM];      // tf32 attn+dwc (proj input)

__device__ __forceinline__ uint32_t f2tf(float f) {
    uint32_t u;
    asm("cvt.rna.tf32.f32 %0, %1;" : "=r"(u) : "f"(f));
    return u;
}
__device__ __forceinline__ void fma2(u64& d, u64 a, u64 b) {
    asm("fma.rn.f32x2 %0, %1, %2, %0;" : "+l"(d) : "l"(a), "l"(b));
}
__device__ __forceinline__ float2 unpack2(u64 v) {
    float2 f;
    asm("mov.b64 {%0,%1}, %2;" : "=f"(f.x), "=f"(f.y) : "l"(v));
    return f;
}
__device__ __forceinline__ u64 pack2(float lo, float hi) {
    u64 r;
    asm("mov.b64 %0, {%1,%2};" : "=l"(r) : "f"(lo), "f"(hi));
    return r;
}

// ======================= fp32 -> tf32 conversion (all operands, one kernel) =======================
__global__ void cvt_all(const float4* __restrict__ x, const float4* __restrict__ qw,
                        const float4* __restrict__ kvw, const float4* __restrict__ pw)
{
    const float4* src;
    uint4* dst;
    int n4;
    switch (blockIdx.y) {
        case 0: src = x;   dst = (uint4*)g_xt;                 n4 = BATCH * NTOK * DIM / 4; break;
        case 1: src = qw;  dst = (uint4*)g_qkvw_t;             n4 = DIM * DIM / 4;          break;
        case 2: src = kvw; dst = (uint4*)(g_qkvw_t + DIM*DIM); n4 = 2 * DIM * DIM / 4;      break;
        default: src = pw; dst = (uint4*)g_pw_t;               n4 = DIM * DIM / 4;          break;
    }
    for (int i = blockIdx.x * blockDim.x + threadIdx.x; i < n4; i += gridDim.x * blockDim.x) {
        float4 v = src[i];
        uint4 o;
        o.x = f2tf(v.x); o.y = f2tf(v.y); o.z = f2tf(v.z); o.w = f2tf(v.w);
        dst[i] = o;
    }
}

// ======================= TF32 tensor-core GEMM, cp.async 4-stage =======================
#define GSTAGES 4
#define STAGE_ELEMS (2 * 128 * 20)
#define GEMM_SMEM_BYTES (GSTAGES * STAGE_ELEMS * 4)   // 81920

__device__ __forceinline__ void cp_async16(uint32_t saddr, const void* gptr) {
    asm volatile("cp.async.cg.shared.global [%0], [%1], 16;" :: "r"(saddr), "l"(gptr));
}
__device__ __forceinline__ void cp_commit() {
    asm volatile("cp.async.commit_group;");
}
template<int N> __device__ __forceinline__ void cp_wait() {
    asm volatile("cp.async.wait_group %0;" :: "n"(N));
}

__device__ __forceinline__ void mma_tf32(float* d, const uint32_t* a, const uint32_t* b) {
    asm volatile(
        "mma.sync.aligned.m16n8k8.row.col.f32.tf32.tf32.f32 "
        "{%0,%1,%2,%3}, {%4,%5,%6,%7}, {%8,%9}, {%0,%1,%2,%3};"
        : "+f"(d[0]), "+f"(d[1]), "+f"(d[2]), "+f"(d[3])
        : "r"(a[0]), "r"(a[1]), "r"(a[2]), "r"(a[3]), "r"(b[0]), "r"(b[1]));
}

__device__ __forceinline__ void tf32_gemm_main(const uint32_t* __restrict__ A,
                                               const uint32_t* __restrict__ W,
                                               int K, float acc[4][4][4])
{
    extern __shared__ uint32_t dsm[];
    const int row0 = blockIdx.y * 128;
    const int col0 = blockIdx.x * 128;
    const int tid  = threadIdx.x;
    const int lane = tid & 31;
    const int warp = tid >> 5;
    const int wm = warp >> 2;
    const int wn = warp & 3;
    const int gid = lane >> 2;
    const int tig = lane & 3;

    const int lr = tid >> 1;
    const int lc = (tid & 1) * 8;

    const uint32_t* Ag = A + (size_t)(row0 + lr) * K + lc;
    const uint32_t* Wg = W + (size_t)(col0 + lr) * K + lc;

    uint32_t smem_base = (uint32_t)__cvta_generic_to_shared(dsm);
    const uint32_t a_dst = smem_base + (uint32_t)(lr * 20 + lc) * 4;
    const uint32_t b_dst = a_dst + 128 * 20 * 4;

    const int NITER = K >> 4;

#pragma unroll
    for (int i = 0; i < 4; i++)
#pragma unroll
        for (int j = 0; j < 4; j++)
#pragma unroll
            for (int r = 0; r < 4; r++) acc[i][j][r] = 0.f;

#pragma unroll
    for (int s = 0; s < GSTAGES - 1; s++) {
        uint32_t so = (uint32_t)(s * STAGE_ELEMS) * 4;
        cp_async16(a_dst + so,      Ag + s * 16);
        cp_async16(a_dst + so + 16, Ag + s * 16 + 4);
        cp_async16(b_dst + so,      Wg + s * 16);
        cp_async16(b_dst + so + 16, Wg + s * 16 + 4);
        cp_commit();
    }

    for (int it = 0; it < NITER; it++) {
        cp_wait<GSTAGES - 2>();
        __syncthreads();

        int nxt = it + GSTAGES - 1;
        if (nxt < NITER) {
            int s = nxt & (GSTAGES - 1);
            uint32_t so = (uint32_t)(s * STAGE_ELEMS) * 4;
            cp_async16(a_dst + so,      Ag + nxt * 16);
            cp_async16(a_dst + so + 16, Ag + nxt * 16 + 4);
            cp_async16(b_dst + so,      Wg + nxt * 16);
            cp_async16(b_dst + so + 16, Wg + nxt * 16 + 4);
        }
        cp_commit();

        const uint32_t* As = dsm + (it & (GSTAGES - 1)) * STAGE_ELEMS;
        const uint32_t* Bs = As + 128 * 20;

#pragma unroll
        for (int kk = 0; kk < 16; kk += 8) {
            uint32_t af[4][4], bf[4][2];
#pragma unroll
            for (int mt = 0; mt < 4; mt++) {
                int r = wm * 64 + mt * 16 + gid;
                af[mt][0] = As[r * 20 + kk + tig];
                af[mt][1] = As[(r + 8) * 20 + kk + tig];
                af[mt][2] = As[r * 20 + kk + tig + 4];
                af[mt][3] = As[(r + 8) * 20 + kk + tig + 4];
            }
#pragma unroll
            for (int nt = 0; nt < 4; nt++) {
                int cb = wn * 32 + nt * 8 + gid;
                bf[nt][0] = Bs[cb * 20 + kk + tig];
                bf[nt][1] = Bs[cb * 20 + kk + tig + 4];
            }
#pragma unroll
            for (int mt = 0; mt < 4; mt++)
#pragma unroll
                for (int nt = 0; nt < 4; nt++)
                    mma_tf32(acc[mt][nt], af[mt], bf[nt]);
        }
    }
}

// merged QKV GEMM; epilogue scatters into head-planar [b][h][n][d] arrays.
__global__ void __launch_bounds__(256, 2) gemm_qkv()
{
    float acc[4][4][4];
    tf32_gemm_main(g_xt, g_qkvw_t, DIM, acc);

    const int row0 = blockIdx.y * 128;
    const int col0 = blockIdx.x * 128;
    const int tid  = threadIdx.x;
    const int lane = tid & 31;
    const int warp = tid >> 5;
    const int wm = warp >> 2, wn = warp & 3;
    const int gid = lane >> 2, tig = lane & 3;

    const int seg = col0 >> 9;                 // 0=q,1=k,2=v
    float* P = (seg == 0) ? g_qh : (seg == 1) ? g_k : g_v;
    const int cseg = col0 & 511;

#pragma unroll
    for (int mt = 0; mt < 4; mt++) {
        int r  = row0 + wm * 64 + mt * 16 + gid;
        int bb = r / NTOK, nn = r % NTOK;
        int r8 = r + 8;
        int bb8 = r8 / NTOK, nn8 = r8 % NTOK;
#pragma unroll
        for (int nt = 0; nt < 4; nt++) {
            int c = cseg + wn * 32 + nt * 8 + 2 * tig;
            int h = c >> 6, d = c & 63;
            *(float2*)&P[(((size_t)(bb * NH + h)) * NTOK + nn) * HD + d] =
                make_float2(acc[mt][nt][0], acc[mt][nt][1]);
            *(float2*)&P[(((size_t)(bb8 * NH + h)) * NTOK + nn8) * HD + d] =
                make_float2(acc[mt][nt][2], acc[mt][nt][3]);
        }
    }
}

__global__ void __launch_bounds__(256, 2) gemm_proj(const float* __restrict__ bias,
                                                    float* __restrict__ out)
{
    float acc[4][4][4];
    tf32_gemm_main(g_attn_t, g_pw_t, DIM, acc);

    const int row0 = blockIdx.y * 128;
    const int col0 = blockIdx.x * 128;
    const int tid  = threadIdx.x;
    const int lane = tid & 31;
    const int warp = tid >> 5;
    const int wm = warp >> 2, wn = warp & 3;
    const int gid = lane >> 2, tig = lane & 3;

#pragma unroll
    for (int mt = 0; mt < 4; mt++) {
        int r = row0 + wm * 64 + mt * 16 + gid;
#pragma unroll
        for (int nt = 0; nt < 4; nt++) {
            int c = col0 + wn * 32 + nt * 8 + 2 * tig;
            float2 bb = *(const float2*)&bias[c];
            *(float2*)&out[(size_t)r * DIM + c] =
                make_float2(acc[mt][nt][0] + bb.x, acc[mt][nt][1] + bb.y);
            *(float2*)&out[(size_t)(r + 8) * DIM + c] =
                make_float2(acc[mt][nt][2] + bb.x, acc[mt][nt][3] + bb.y);
        }
    }
}

// ======================= bias precompute =======================
__device__ __forceinline__ float bilin7(const float* __restrict__ t, int i, int j)
{
    float si = (i - 1.5f) * 0.25f;
    float sj = (j - 1.5f) * 0.25f;
    float fi = floorf(si), fj = floorf(sj);
    int i0 = (int)fi, j0 = (int)fj;
    float wi = si - fi, wj = sj - fj;
    int i0c = max(0, min(6, i0)), i1c = max(0, min(6, i0 + 1));
    int j0c = max(0, min(6, j0)), j1c = max(0, min(6, j0 + 1));
    float v00 = t[i0c * 7 + j0c], v01 = t[i0c * 7 + j1c];
    float v10 = t[i1c * 7 + j0c], v11 = t[i1c * 7 + j1c];
    return (1.f - wi) * ((1.f - wj) * v00 + wj * v01)
         +        wi  * ((1.f - wj) * v10 + wj * v11);
}

__global__ void build_bias(const float* __restrict__ an_bias, const float* __restrict__ na_bias,
                           const float* __restrict__ ah_bias, const float* __restrict__ aw_bias,
                           const float* __restrict__ ha_bias, const float* __restrict__ wa_bias)
{
    int ha = blockIdx.x;
    int h = ha / DA, a = ha % DA;
    int n = threadIdx.x;
    int i = n / WW, j = n % WW;
    g_pos_bias[(size_t)ha * NTOK + n] =
        bilin7(an_bias + (size_t)ha * 49, i, j) + ah_bias[ha * HH + i] + aw_bias[ha * WW + j];
    g_agent_bias[((size_t)h * NTOK + n) * DA + a] =
        bilin7(na_bias + (size_t)ha * 49, i, j)
        + ha_bias[(h * HH + i) * DA + a] + wa_bias[(h * WW + j) * DA + a];
}

// ======================= agent attention (pool + mma scores + softmax + AV) =======================
// one block per (b,h), 512 threads.
// smem floats: sS[784][53] | sAg[56][68] | sKt[112][68]
#define AS_SS   0
#define AS_SAG  (NTOK * 53)                        // 41552
#define AS_SKT  (AS_SAG + 56 * 68)                 // 45360
#define AS_SMEM_FLOATS (AS_SKT + 112 * 68)         // 52976
#define AS_SMEM_BYTES (AS_SMEM_FLOATS * 4)         // 211904

__global__ void __launch_bounds__(512, 1) agent_attn()
{
    extern __shared__ float sm[];
    float* sS  = sm + AS_SS;               // [784][53] scores transposed [n][a]
    float* sAg = sm + AS_SAG;              // [56][68]  tf32-rounded scaled agents (rows 49..55 zero)
    float* sKt = sm + AS_SKT;              // [112][68] staged K tile
    __shared__ float sInv[DA];
    const int h = blockIdx.x, b = blockIdx.y;
    const int tid = threadIdx.x;
    const int warp = tid >> 5, lane = tid & 31;
    const int gid = lane >> 2, tig = lane & 3;

    const float* qpl = g_qh + ((size_t)(b * NH + h)) * NTOK * HD;
    const float* kpl = g_k  + ((size_t)(b * NH + h)) * NTOK * HD;
    const float* vpl = g_v  + ((size_t)(b * NH + h)) * NTOK * HD;

    uint32_t smem_base = (uint32_t)__cvta_generic_to_shared(sm);

    // ---- P0: pooled agent (4x4 avg over q image) * 1/8, tf32-rounded -> sAg + g_ag ----
    for (int i = tid; i < DA * HD; i += 512) {
        int a = i >> 6, d = i & 63;
        int ai = a / 7, aj = a % 7;
        const float* qb = qpl + ((ai * 4) * WW + aj * 4) * HD + d;
        float s = 0.f;
#pragma unroll
        for (int di = 0; di < 4; di++)
#pragma unroll
            for (int dj = 0; dj < 4; dj++)
                s += qb[(di * WW + dj) * HD];
        float v = __uint_as_float(f2tf(s * 0.0078125f));   // (1/16)*(1/8), pre-rounded to tf32
        sAg[a * 68 + d] = v;
        g_ag[((size_t)(b * NH + h)) * DA * HD + i] = v;
    }
    // zero pad rows 49..55 of sAg
    for (int i = tid; i < 7 * 68; i += 512)
        sAg[(DA + i / 68) * 68 + (i % 68)] = 0.f;
    // init sS[n][a] = pos_bias[h][a][n]  (coalesced read, odd-pitch write)
    {
        const float* pb = g_pos_bias + (size_t)h * DA * NTOK;
        for (int i = tid; i < DA * NTOK; i += 512) {
            int a = i / NTOK, n = i % NTOK;
            sS[n * 53 + a] = pb[i];
        }
    }
    __syncthreads();

    // ---- P1: scores via mma, 7 tiles of 112 tokens: sS[n][a] += K[n].Ag[a] ----
    for (int t = 0; t < 7; t++) {
        // stage K tile (112 x 64) via cp.async
        for (int i = tid; i < 112 * 16; i += 512) {
            int r = i >> 4, c = i & 15;
            cp_async16(smem_base + (uint32_t)(AS_SKT + r * 68 + c * 4) * 4,
                       kpl + (size_t)(t * 112 + r) * HD + c * 4);
        }
        cp_commit();
        cp_wait<0>();
        __syncthreads();

        if (warp < 7) {
            const int m0 = warp * 16;
            uint32_t af[8][4];
#pragma unroll
            for (int c = 0; c < 8; c++) {
                const float* r0 = sKt + (m0 + gid) * 68 + 8 * c + tig;
                const float* r1 = r0 + 8 * 68;
                af[c][0] = f2tf(r0[0]);
                af[c][1] = f2tf(r1[0]);
                af[c][2] = f2tf(r0[4]);
                af[c][3] = f2tf(r1[4]);
            }
#pragma unroll
            for (int j = 0; j < 7; j++) {
                float acc[4] = {0.f, 0.f, 0.f, 0.f};
#pragma unroll
                for (int c = 0; c < 8; c++) {
                    uint32_t bf[2];
                    const float* br = sAg + (8 * j + gid) * 68 + 8 * c + tig;
                    bf[0] = __float_as_uint(br[0]);   // pre-rounded tf32
                    bf[1] = __float_as_uint(br[4]);
                    mma_tf32(acc, af[c], bf);
                }
                int col = 8 * j + 2 * tig;
                float* s0 = sS + (t * 112 + m0 + gid) * 53 + col;
                float* s1 = s0 + 8 * 53;
                if (col < DA)     { s0[0] += acc[0]; s1[0] += acc[2]; }
                if (col + 1 < DA) { s0[1] += acc[1]; s1[1] += acc[3]; }
            }
        }
        __syncthreads();
    }

    // ---- P2: softmax over n per agent (warp per agent; stride-53 column walk, conflict-free) ----
    for (int a = warp; a < DA; a += 16) {
        float m = -1e30f;
        for (int n = lane; n < NTOK; n += 32) m = fmaxf(m, sS[n * 53 + a]);
#pragma unroll
        for (int o = 16; o > 0; o >>= 1) m = fmaxf(m, __shfl_xor_sync(0xffffffff, m, o));
        float s = 0.f;
        for (int n = lane; n < NTOK; n += 32) {
            float e = __expf(sS[n * 53 + a] - m);
            sS[n * 53 + a] = e; s += e;
        }
#pragma unroll
        for (int o = 16; o > 0; o >>= 1) s += __shfl_xor_sync(0xffffffff, s, o);
        if (lane == 0) sInv[a] = 1.f / s;
    }
    __syncthreads();

    // ---- P3: agent_v[a][d] -> g_avT [d][a] (warp owns a = warp+16i; lane owns d-pair) ----
    {
        u64 acc[4];
#pragma unroll
        for (int i = 0; i < 4; i++) acc[i] = 0;
        const u64* vb = (const u64*)vpl + lane;
#pragma unroll 4
        for (int n = 0; n < NTOK; n++) {
            u64 vv = vb[n * 32];
#pragma unroll
            for (int i = 0; i < 4; i++) {
                int a = warp + 16 * i;
                if (a < DA) {
                    float p = sS[n * 53 + a];
                    fma2(acc[i], pack2(p, p), vv);
                }
            }
        }
        float* avT = g_avT + ((size_t)(b * NH + h)) * HD * DA;
#pragma unroll
        for (int i = 0; i < 4; i++) {
            int a = warp + 16 * i;
            if (a < DA) {
                float2 f = unpack2(acc[i]);
                float inv = sInv[a];
                avT[(2 * lane) * DA + a]     = f.x * inv;
                avT[(2 * lane + 1) * DA + a] = f.y * inv;
            }
        }
    }
}

// ======================= q attention via tensor cores =======================
// grid (7 tiles of 112 tokens, NH, BATCH), 256 threads = 8 warps (warps 0-6 do mma).
// smem floats: sQ[112][68] | sAg[56][68] | sAvT[64][60] | sS[112][60] | sInv[112]
#define QT_SQ   0
#define QT_SAG  (112 * 68)                         // 7616
#define QT_SAVT (QT_SAG + 56 * 68)                 // 11424
#define QT_SS   (QT_SAVT + 64 * 60)                // 15264
#define QT_SINV (QT_SS + 112 * 60)                 // 21984
#define QT_SMEM_FLOATS (QT_SINV + 112)             // 22096
#define QT_SMEM_BYTES (QT_SMEM_FLOATS * 4)         // 88384

__global__ void __launch_bounds__(256, 2) q_attn_mma()
{
    extern __shared__ float sm[];
    const int tile = blockIdx.x, h = blockIdx.y, b = blockIdx.z;
    const int n0 = tile * 112;
    const int tid = threadIdx.x;
    const int lane = tid & 31, warp = tid >> 5;
    const int gid = lane >> 2, tig = lane & 3;

    const float* qpl = g_qh + ((size_t)(b * NH + h)) * NTOK * HD;
    const float* agp = g_ag + ((size_t)(b * NH + h)) * DA * HD;
    const float* avT = g_avT + ((size_t)(b * NH + h)) * HD * DA;

    uint32_t smem_base = (uint32_t)__cvta_generic_to_shared(sm);

    // ---- stage: Q tile + Ag via cp.async; AvT + bias + pads via scalar ----
    for (int i = tid; i < 112 * 16; i += 256) {
        int r = i >> 4, c = i & 15;
        cp_async16(smem_base + (uint32_t)(QT_SQ + r * 68 + c * 4) * 4,
                   qpl + (size_t)(n0 + r) * HD + c * 4);
    }
    for (int i = tid; i < DA * 16; i += 256) {
        int r = i >> 4, c = i & 15;
        cp_async16(smem_base + (uint32_t)(QT_SAG + r * 68 + c * 4) * 4,
                   agp + (size_t)r * HD + c * 4);
    }
    cp_commit();
    // zero Ag pad rows 49..55
    for (int i = tid; i < 7 * 68; i += 256)
        sm[QT_SAG + (DA + i / 68) * 68 + (i % 68)] = 0.f;
    // AvT rows [d][a], pad cols 49..55 with 0
    for (int i = tid; i < 64 * 56; i += 256) {
        int r = i / 56, c = i % 56;
        sm[QT_SAVT + r * 60 + c] = (c < DA) ? avT[r * DA + c] : 0.f;
    }
    // sS init = agent_bias [h][n][a] (cols 49..55 = 0)
    {
        const float* abp = g_agent_bias + ((size_t)h * NTOK + n0) * DA;
        for (int i = tid; i < 112 * 56; i += 256) {
            int r = i / 56, c = i % 56;
            sm[QT_SS + r * 60 + c] = (c < DA) ? abp[r * DA + c] : 0.f;
        }
    }
    cp_wait<0>();
    __syncthreads();

    // ---- phase A: sS += Q . Ag^T  (M=112, N=56, K=64) ----
    if (warp < 7) {
        const int m0 = warp * 16;
        uint32_t af[8][4];
#pragma unroll
        for (int c = 0; c < 8; c++) {
            const float* r0 = sm + QT_SQ + (m0 + gid) * 68 + 8 * c + tig;
            const float* r1 = r0 + 8 * 68;
            af[c][0] = f2tf(r0[0]);
            af[c][1] = f2tf(r1[0]);
            af[c][2] = f2tf(r0[4]);
            af[c][3] = f2tf(r1[4]);
        }
#pragma unroll
        for (int j = 0; j < 7; j++) {
            float acc[4] = {0.f, 0.f, 0.f, 0.f};
#pragma unroll
            for (int c = 0; c < 8; c++) {
                uint32_t bf[2];
                const float* br = sm + QT_SAG + (8 * j + gid) * 68 + 8 * c + tig;
                bf[0] = f2tf(br[0]);
                bf[1] = f2tf(br[4]);
                mma_tf32(acc, af[c], bf);
            }
            int col = 8 * j + 2 * tig;
            float* s0 = sm + QT_SS + (m0 + gid) * 60 + col;
            float* s1 = s0 + 8 * 60;
            s0[0] += acc[0]; s0[1] += acc[1];
            s1[0] += acc[2]; s1[1] += acc[3];
        }
    }
    __syncthreads();

    // ---- phase B: per-token softmax over agents ----
    if (tid < 112) {
        float* row = sm + QT_SS + tid * 60;
        float m = -1e30f;
        for (int a = 0; a < DA; a++) m = fmaxf(m, row[a]);
        float s = 0.f;
        for (int a = 0; a < DA; a++) { float e = __expf(row[a] - m); row[a] = e; s += e; }
#pragma unroll
        for (int a = DA; a < 56; a++) row[a] = 0.f;
        sm[QT_SINV + tid] = 1.f / s;
    }
    __syncthreads();

    // ---- phase C: O = P . AvT^T  (M=112, N=64, K=56), scale rows by 1/sum ----
    if (warp < 7) {
        const int m0 = warp * 16;
        uint32_t af[7][4];
#pragma unroll
        for (int c = 0; c < 7; c++) {
            const float* r0 = sm + QT_SS + (m0 + gid) * 60 + 8 * c + tig;
            const float* r1 = r0 + 8 * 60;
            af[c][0] = f2tf(r0[0]);
            af[c][1] = f2tf(r1[0]);
            af[c][2] = f2tf(r0[4]);
            af[c][3] = f2tf(r1[4]);
        }
        float inv0 = sm[QT_SINV + m0 + gid];
        float inv8 = sm[QT_SINV + m0 + gid + 8];
        float* orow0 = g_attn + ((size_t)(b * NTOK + n0 + m0 + gid)) * DIM + h * HD;
        float* orow8 = orow0 + (size_t)8 * DIM;
#pragma unroll
        for (int j = 0; j < 8; j++) {
            float acc[4] = {0.f, 0.f, 0.f, 0.f};
#pragma unroll
            for (int c = 0; c < 7; c++) {
                uint32_t bf[2];
                const float* br = sm + QT_SAVT + (8 * j + gid) * 60 + 8 * c + tig;
                bf[0] = f2tf(br[0]);
                bf[1] = f2tf(br[4]);
                mma_tf32(acc, af[c], bf);
            }
            int col = 8 * j + 2 * tig;
            *(float2*)&orow0[col] = make_float2(acc[0] * inv0, acc[1] * inv0);
            *(float2*)&orow8[col] = make_float2(acc[2] * inv8, acc[3] * inv8);
        }
    }
}

// ======================= depthwise 3x3 conv on v, + attn, -> tf32 =======================
__global__ void dwc_add(const float* __restrict__ w, const float* __restrict__ bias)
{
    int n = blockIdx.x, b = blockIdx.y;
    int c = threadIdx.x;
    int h = c >> 6, d = c & 63;
    int i = n / WW, j = n % WW;
    const float* vpl = g_v + ((size_t)(b * NH + h)) * NTOK * HD + d;
    float acc = bias[c];
#pragma unroll
    for (int di = 0; di < 3; di++) {
        int ii = i + di - 1;
        if (ii < 0 || ii > HH - 1) continue;
#pragma unroll
        for (int dj = 0; dj < 3; dj++) {
            int jj = j + dj - 1;
            if (jj < 0 || jj > WW - 1) continue;
            acc = fmaf(w[c * 9 + di * 3 + dj], vpl[(size_t)(ii * WW + jj) * HD], acc);
        }
    }
    size_t idx = ((size_t)(b * NTOK + n)) * DIM + c;
    g_attn_t[idx] = f2tf(g_attn[idx] + acc);
}

// ======================= launch =======================
extern "C" void kernel_launch(void* const* d_in, const int* in_sizes, int n_in,
                              void* d_out, int out_size)
{
    const float* x       = (const float*)d_in[0];
    const float* q_w     = (const float*)d_in[1];
    const float* kv_w    = (const float*)d_in[2];
    const float* proj_w  = (const float*)d_in[3];
    const float* proj_b  = (const float*)d_in[4];
    const float* dwc_w   = (const float*)d_in[5];
    const float* dwc_b   = (const float*)d_in[6];
    const float* an_bias = (const float*)d_in[7];
    const float* na_bias = (const float*)d_in[8];
    const float* ah_bias = (const float*)d_in[9];
    const float* aw_bias = (const float*)d_in[10];
    const float* ha_bias = (const float*)d_in[11];
    const float* wa_bias = (const float*)d_in[12];
    float* out = (float*)d_out;

    cudaFuncSetAttribute(gemm_qkv,   cudaFuncAttributeMaxDynamicSharedMemorySize, GEMM_SMEM_BYTES);
    cudaFuncSetAttribute(gemm_proj,  cudaFuncAttributeMaxDynamicSharedMemorySize, GEMM_SMEM_BYTES);
    cudaFuncSetAttribute(agent_attn, cudaFuncAttributeMaxDynamicSharedMemorySize, AS_SMEM_BYTES);
    cudaFuncSetAttribute(q_attn_mma, cudaFuncAttributeMaxDynamicSharedMemorySize, QT_SMEM_BYTES);

    // 1: convert operands to tf32
    cvt_all<<<dim3(512, 4), 256>>>((const float4*)x, (const float4*)q_w,
                                   (const float4*)kv_w, (const float4*)proj_w);
    // 2: merged QKV GEMM (head-planar epilogue)
    gemm_qkv<<<dim3(3 * DIM / 128, (BATCH * NTOK) / 128), 256, GEMM_SMEM_BYTES>>>();
    // 3: bias tables
    build_bias<<<NH * DA, NTOK>>>(an_bias, na_bias, ah_bias, aw_bias, ha_bias, wa_bias);
    // 4: agent attention (pool + mma scores + softmax + AV)  <-- ncu-profiled slot
    agent_attn<<<dim3(NH, BATCH), 512, AS_SMEM_BYTES>>>();
    // 5: q attention via tensor cores
    q_attn_mma<<<dim3(7, NH, BATCH), 256, QT_SMEM_BYTES>>>();
    // 6: depthwise conv + add + tf32 convert
    dwc_add<<<dim3(NTOK, BATCH), DIM>>>(dwc_w, dwc_b);
    // 7: output projection
    gemm_proj<<<dim3(DIM / 128, (BATCH * NTOK) / 128), 256, GEMM_SMEM_BYTES>>>(proj_b, out);
}

// round 15
// speedup vs baseline: 1.3696x; 1.0810x over previous
#include <cuda_runtime.h>
#include <math.h>
#include <stdint.h>

// Problem constants
#define BATCH 32
#define NTOK  784
#define DIM   512
#define NH    8
#define HD    64
#define HH    28
#define WW    28
#define DA    49
#define NTILE 7
#define TILE  112

typedef unsigned long long u64;

// -------- scratch (__device__ globals; no allocations allowed) --------
__device__ float    g_qh[BATCH * NH * NTOK * HD];
__device__ float    g_k [BATCH * NH * NTOK * HD];
__device__ float    g_v [BATCH * NH * NTOK * HD];
__device__ float    g_ag [BATCH * NH * DA * HD];       // scaled pooled agents (tf32-rounded)
__device__ float    g_avT[BATCH * NH * HD * DA];       // agent_v transposed [b][h][d][a]
__device__ float    g_avp[NTILE * BATCH * NH * DA * HD]; // raw partial exp.V  [t][bh][a][d]
__device__ float    g_pm [NTILE * BATCH * NH * DA];    // partial max
__device__ float    g_ps [NTILE * BATCH * NH * DA];    // partial sum
__device__ float    g_pos_bias[NH * DA * NTOK];        // [h,a,n]
__device__ float    g_agent_bias[NH * NTOK * DA];      // [h,n,a]
__device__ float    g_attn [BATCH * NTOK * DIM];       // fp32 attn staging (pre-dwc)
__device__ uint32_t g_xt   [BATCH * NTOK * DIM];
__device__ uint32_t g_qkvw_t[3 * DIM * DIM];
__device__ uint32_t g_pw_t [DIM * DIM];
__device__ uint32_t g_attn_t[BATCH * NTOK * DIM];

__device__ __forceinline__ uint32_t f2tf(float f) {
    uint32_t u;
    asm("cvt.rna.tf32.f32 %0, %1;" : "=r"(u) : "f"(f));
    return u;
}
__device__ __forceinline__ void fma2(u64& d, u64 a, u64 b) {
    asm("fma.rn.f32x2 %0, %1, %2, %0;" : "+l"(d) : "l"(a), "l"(b));
}
__device__ __forceinline__ float2 unpack2(u64 v) {
    float2 f;
    asm("mov.b64 {%0,%1}, %2;" : "=f"(f.x), "=f"(f.y) : "l"(v));
    return f;
}
__device__ __forceinline__ u64 pack2(float lo, float hi) {
    u64 r;
    asm("mov.b64 %0, {%1,%2};" : "=l"(r) : "f"(lo), "f"(hi));
    return r;
}

// ======================= fp32 -> tf32 conversion =======================
__global__ void cvt_all(const float4* __restrict__ x, const float4* __restrict__ qw,
                        const float4* __restrict__ kvw, const float4* __restrict__ pw)
{
    const float4* src;
    uint4* dst;
    int n4;
    switch (blockIdx.y) {
        case 0: src = x;   dst = (uint4*)g_xt;                 n4 = BATCH * NTOK * DIM / 4; break;
        case 1: src = qw;  dst = (uint4*)g_qkvw_t;             n4 = DIM * DIM / 4;          break;
        case 2: src = kvw; dst = (uint4*)(g_qkvw_t + DIM*DIM); n4 = 2 * DIM * DIM / 4;      break;
        default: src = pw; dst = (uint4*)g_pw_t;               n4 = DIM * DIM / 4;          break;
    }
    for (int i = blockIdx.x * blockDim.x + threadIdx.x; i < n4; i += gridDim.x * blockDim.x) {
        float4 v = src[i];
        uint4 o;
        o.x = f2tf(v.x); o.y = f2tf(v.y); o.z = f2tf(v.z); o.w = f2tf(v.w);
        dst[i] = o;
    }
}

// ======================= TF32 tensor-core GEMM, cp.async 4-stage =======================
#define GSTAGES 4
#define STAGE_ELEMS (2 * 128 * 20)
#define GEMM_SMEM_BYTES (GSTAGES * STAGE_ELEMS * 4)

__device__ __forceinline__ void cp_async16(uint32_t saddr, const void* gptr) {
    asm volatile("cp.async.cg.shared.global [%0], [%1], 16;" :: "r"(saddr), "l"(gptr));
}
__device__ __forceinline__ void cp_commit() {
    asm volatile("cp.async.commit_group;");
}
template<int N> __device__ __forceinline__ void cp_wait() {
    asm volatile("cp.async.wait_group %0;" :: "n"(N));
}

__device__ __forceinline__ void mma_tf32(float* d, const uint32_t* a, const uint32_t* b) {
    asm volatile(
        "mma.sync.aligned.m16n8k8.row.col.f32.tf32.tf32.f32 "
        "{%0,%1,%2,%3}, {%4,%5,%6,%7}, {%8,%9}, {%0,%1,%2,%3};"
        : "+f"(d[0]), "+f"(d[1]), "+f"(d[2]), "+f"(d[3])
        : "r"(a[0]), "r"(a[1]), "r"(a[2]), "r"(a[3]), "r"(b[0]), "r"(b[1]));
}

__device__ __forceinline__ void tf32_gemm_main(const uint32_t* __restrict__ A,
                                               const uint32_t* __restrict__ W,
                                               int K, float acc[4][4][4])
{
    extern __shared__ uint32_t dsm[];
    const int row0 = blockIdx.y * 128;
    const int col0 = blockIdx.x * 128;
    const int tid  = threadIdx.x;
    const int lane = tid & 31;
    const int warp = tid >> 5;
    const int wm = warp >> 2;
    const int wn = warp & 3;
    const int gid = lane >> 2;
    const int tig = lane & 3;

    const int lr = tid >> 1;
    const int lc = (tid & 1) * 8;

    const uint32_t* Ag = A + (size_t)(row0 + lr) * K + lc;
    const uint32_t* Wg = W + (size_t)(col0 + lr) * K + lc;

    uint32_t smem_base = (uint32_t)__cvta_generic_to_shared(dsm);
    const uint32_t a_dst = smem_base + (uint32_t)(lr * 20 + lc) * 4;
    const uint32_t b_dst = a_dst + 128 * 20 * 4;

    const int NITER = K >> 4;

#pragma unroll
    for (int i = 0; i < 4; i++)
#pragma unroll
        for (int j = 0; j < 4; j++)
#pragma unroll
            for (int r = 0; r < 4; r++) acc[i][j][r] = 0.f;

#pragma unroll
    for (int s = 0; s < GSTAGES - 1; s++) {
        uint32_t so = (uint32_t)(s * STAGE_ELEMS) * 4;
        cp_async16(a_dst + so,      Ag + s * 16);
        cp_async16(a_dst + so + 16, Ag + s * 16 + 4);
        cp_async16(b_dst + so,      Wg + s * 16);
        cp_async16(b_dst + so + 16, Wg + s * 16 + 4);
        cp_commit();
    }

    for (int it = 0; it < NITER; it++) {
        cp_wait<GSTAGES - 2>();
        __syncthreads();

        int nxt = it + GSTAGES - 1;
        if (nxt < NITER) {
            int s = nxt & (GSTAGES - 1);
            uint32_t so = (uint32_t)(s * STAGE_ELEMS) * 4;
            cp_async16(a_dst + so,      Ag + nxt * 16);
            cp_async16(a_dst + so + 16, Ag + nxt * 16 + 4);
            cp_async16(b_dst + so,      Wg + nxt * 16);
            cp_async16(b_dst + so + 16, Wg + nxt * 16 + 4);
        }
        cp_commit();

        const uint32_t* As = dsm + (it & (GSTAGES - 1)) * STAGE_ELEMS;
        const uint32_t* Bs = As + 128 * 20;

#pragma unroll
        for (int kk = 0; kk < 16; kk += 8) {
            uint32_t af[4][4], bf[4][2];
#pragma unroll
            for (int mt = 0; mt < 4; mt++) {
                int r = wm * 64 + mt * 16 + gid;
                af[mt][0] = As[r * 20 + kk + tig];
                af[mt][1] = As[(r + 8) * 20 + kk + tig];
                af[mt][2] = As[r * 20 + kk + tig + 4];
                af[mt][3] = As[(r + 8) * 20 + kk + tig + 4];
            }
#pragma unroll
            for (int nt = 0; nt < 4; nt++) {
                int cb = wn * 32 + nt * 8 + gid;
                bf[nt][0] = Bs[cb * 20 + kk + tig];
                bf[nt][1] = Bs[cb * 20 + kk + tig + 4];
            }
#pragma unroll
            for (int mt = 0; mt < 4; mt++)
#pragma unroll
                for (int nt = 0; nt < 4; nt++)
                    mma_tf32(acc[mt][nt], af[mt], bf[nt]);
        }
    }
}

__global__ void __launch_bounds__(256, 2) gemm_qkv()
{
    float acc[4][4][4];
    tf32_gemm_main(g_xt, g_qkvw_t, DIM, acc);

    const int row0 = blockIdx.y * 128;
    const int col0 = blockIdx.x * 128;
    const int tid  = threadIdx.x;
    const int lane = tid & 31;
    const int warp = tid >> 5;
    const int wm = warp >> 2, wn = warp & 3;
    const int gid = lane >> 2, tig = lane & 3;

    const int seg = col0 >> 9;
    float* P = (seg == 0) ? g_qh : (seg == 1) ? g_k : g_v;
    const int cseg = col0 & 511;

#pragma unroll
    for (int mt = 0; mt < 4; mt++) {
        int r  = row0 + wm * 64 + mt * 16 + gid;
        int bb = r / NTOK, nn = r % NTOK;
        int r8 = r + 8;
        int bb8 = r8 / NTOK, nn8 = r8 % NTOK;
#pragma unroll
        for (int nt = 0; nt < 4; nt++) {
            int c = cseg + wn * 32 + nt * 8 + 2 * tig;
            int h = c >> 6, d = c & 63;
            *(float2*)&P[(((size_t)(bb * NH + h)) * NTOK + nn) * HD + d] =
                make_float2(acc[mt][nt][0], acc[mt][nt][1]);
            *(float2*)&P[(((size_t)(bb8 * NH + h)) * NTOK + nn8) * HD + d] =
                make_float2(acc[mt][nt][2], acc[mt][nt][3]);
        }
    }
}

__global__ void __launch_bounds__(256, 2) gemm_proj(const float* __restrict__ bias,
                                                    float* __restrict__ out)
{
    float acc[4][4][4];
    tf32_gemm_main(g_attn_t, g_pw_t, DIM, acc);

    const int row0 = blockIdx.y * 128;
    const int col0 = blockIdx.x * 128;
    const int tid  = threadIdx.x;
    const int lane = tid & 31;
    const int warp = tid >> 5;
    const int wm = warp >> 2, wn = warp & 3;
    const int gid = lane >> 2, tig = lane & 3;

#pragma unroll
    for (int mt = 0; mt < 4; mt++) {
        int r = row0 + wm * 64 + mt * 16 + gid;
#pragma unroll
        for (int nt = 0; nt < 4; nt++) {
            int c = col0 + wn * 32 + nt * 8 + 2 * tig;
            float2 bb = *(const float2*)&bias[c];
            *(float2*)&out[(size_t)r * DIM + c] =
                make_float2(acc[mt][nt][0] + bb.x, acc[mt][nt][1] + bb.y);
            *(float2*)&out[(size_t)(r + 8) * DIM + c] =
                make_float2(acc[mt][nt][2] + bb.x, acc[mt][nt][3] + bb.y);
        }
    }
}

// ======================= bias precompute =======================
__device__ __forceinline__ float bilin7(const float* __restrict__ t, int i, int j)
{
    float si = (i - 1.5f) * 0.25f;
    float sj = (j - 1.5f) * 0.25f;
    float fi = floorf(si), fj = floorf(sj);
    int i0 = (int)fi, j0 = (int)fj;
    float wi = si - fi, wj = sj - fj;
    int i0c = max(0, min(6, i0)), i1c = max(0, min(6, i0 + 1));
    int j0c = max(0, min(6, j0)), j1c = max(0, min(6, j0 + 1));
    float v00 = t[i0c * 7 + j0c], v01 = t[i0c * 7 + j1c];
    float v10 = t[i1c * 7 + j0c], v11 = t[i1c * 7 + j1c];
    return (1.f - wi) * ((1.f - wj) * v00 + wj * v01)
         +        wi  * ((1.f - wj) * v10 + wj * v11);
}

__global__ void build_bias(const float* __restrict__ an_bias, const float* __restrict__ na_bias,
                           const float* __restrict__ ah_bias, const float* __restrict__ aw_bias,
                           const float* __restrict__ ha_bias, const float* __restrict__ wa_bias)
{
    int ha = blockIdx.x;
    int h = ha / DA, a = ha % DA;
    int n = threadIdx.x;
    int i = n / WW, j = n % WW;
    g_pos_bias[(size_t)ha * NTOK + n] =
        bilin7(an_bias + (size_t)ha * 49, i, j) + ah_bias[ha * HH + i] + aw_bias[ha * WW + j];
    g_agent_bias[((size_t)h * NTOK + n) * DA + a] =
        bilin7(na_bias + (size_t)ha * 49, i, j)
        + ha_bias[(h * HH + i) * DA + a] + wa_bias[(h * WW + j) * DA + a];
}

// ======================= pooled agents (4x4 avg of q, scaled, tf32-rounded) =======================
__global__ void pool_agent()
{
    int h = blockIdx.x, b = blockIdx.y;
    int tid = threadIdx.x;
    const float* qpl = g_qh + ((size_t)(b * NH + h)) * NTOK * HD;
    float* agp = g_ag + ((size_t)(b * NH + h)) * DA * HD;
    for (int i = tid; i < DA * HD; i += 256) {
        int a = i >> 6, d = i & 63;
        int ai = a / 7, aj = a % 7;
        const float* qb = qpl + ((ai * 4) * WW + aj * 4) * HD + d;
        float s = 0.f;
#pragma unroll
        for (int di = 0; di < 4; di++)
#pragma unroll
            for (int dj = 0; dj < 4; dj++)
                s += qb[(di * WW + dj) * HD];
        agp[i] = __uint_as_float(f2tf(s * 0.0078125f));   // (1/16)*(1/8), pre-rounded tf32
    }
}

// ======================= agent attention partial (per 112-token tile) =======================
// grid (7, NH, BATCH), 256 threads.
// smem floats: sKt[112][68] | sVt[112][68] | sAg[56][68] | sS[112][53]
#define AP_SKT 0
#define AP_SVT (TILE * 68)                      // 7616
#define AP_SAG (AP_SVT + TILE * 68)             // 15232
#define AP_SS  (AP_SAG + 56 * 68)               // 19040
#define AP_SMEM_FLOATS (AP_SS + TILE * 53)      // 24976
#define AP_SMEM_BYTES (AP_SMEM_FLOATS * 4)      // 99904

__global__ void __launch_bounds__(256, 2) agent_partial()
{
    extern __shared__ float sm[];
    __shared__ float sM[DA], sSum[DA];
    const int t = blockIdx.x, h = blockIdx.y, b = blockIdx.z;
    const int n0 = t * TILE;
    const int bh = b * NH + h;
    const int tid = threadIdx.x;
    const int lane = tid & 31, warp = tid >> 5;
    const int gid = lane >> 2, tig = lane & 3;

    const float* kpl = g_k  + ((size_t)bh) * NTOK * HD;
    const float* vpl = g_v  + ((size_t)bh) * NTOK * HD;
    const float* agp = g_ag + ((size_t)bh) * DA * HD;

    uint32_t smem_base = (uint32_t)__cvta_generic_to_shared(sm);

    // stage K, V tiles + Ag via cp.async
    for (int i = tid; i < TILE * 16; i += 256) {
        int r = i >> 4, c = i & 15;
        cp_async16(smem_base + (uint32_t)(AP_SKT + r * 68 + c * 4) * 4,
                   kpl + (size_t)(n0 + r) * HD + c * 4);
        cp_async16(smem_base + (uint32_t)(AP_SVT + r * 68 + c * 4) * 4,
                   vpl + (size_t)(n0 + r) * HD + c * 4);
    }
    for (int i = tid; i < DA * 16; i += 256) {
        int r = i >> 4, c = i & 15;
        cp_async16(smem_base + (uint32_t)(AP_SAG + r * 68 + c * 4) * 4,
                   agp + (size_t)r * HD + c * 4);
    }
    cp_commit();
    // zero Ag pad rows 49..55
    for (int i = tid; i < 7 * 68; i += 256)
        sm[AP_SAG + (DA + i / 68) * 68 + (i % 68)] = 0.f;
    // init sS[n][a] = pos_bias[h][a][n0+n]
    {
        const float* pb = g_pos_bias + (size_t)h * DA * NTOK + n0;
        for (int i = tid; i < DA * TILE; i += 256) {
            int a = i / TILE, n = i % TILE;
            sm[AP_SS + n * 53 + a] = pb[a * NTOK + n];
        }
    }
    cp_wait<0>();
    __syncthreads();

    // scores via mma: sS[n][a] += K[n].Ag[a]  (warps 0..6, 16-row m-tiles)
    if (warp < 7) {
        const int m0 = warp * 16;
        uint32_t af[8][4];
#pragma unroll
        for (int c = 0; c < 8; c++) {
            const float* r0 = sm + AP_SKT + (m0 + gid) * 68 + 8 * c + tig;
            const float* r1 = r0 + 8 * 68;
            af[c][0] = f2tf(r0[0]);
            af[c][1] = f2tf(r1[0]);
            af[c][2] = f2tf(r0[4]);
            af[c][3] = f2tf(r1[4]);
        }
#pragma unroll
        for (int j = 0; j < 7; j++) {
            float acc[4] = {0.f, 0.f, 0.f, 0.f};
#pragma unroll
            for (int c = 0; c < 8; c++) {
                uint32_t bf[2];
                const float* br = sm + AP_SAG + (8 * j + gid) * 68 + 8 * c + tig;
                bf[0] = __float_as_uint(br[0]);   // pre-rounded tf32
                bf[1] = __float_as_uint(br[4]);
                mma_tf32(acc, af[c], bf);
            }
            int col = 8 * j + 2 * tig;
            float* s0 = sm + AP_SS + (m0 + gid) * 53 + col;
            float* s1 = s0 + 8 * 53;
            if (col < DA)     { s0[0] += acc[0]; s1[0] += acc[2]; }
            if (col + 1 < DA) { s0[1] += acc[1]; s1[1] += acc[3]; }
        }
    }
    __syncthreads();

    // partial softmax per agent column over this tile's 112 rows
    for (int a = warp; a < DA; a += 8) {
        float m = -1e30f;
        for (int n = lane; n < TILE; n += 32) m = fmaxf(m, sm[AP_SS + n * 53 + a]);
#pragma unroll
        for (int o = 16; o > 0; o >>= 1) m = fmaxf(m, __shfl_xor_sync(0xffffffff, m, o));
        float s = 0.f;
        for (int n = lane; n < TILE; n += 32) {
            float e = __expf(sm[AP_SS + n * 53 + a] - m);
            sm[AP_SS + n * 53 + a] = e; s += e;
        }
#pragma unroll
        for (int o = 16; o > 0; o >>= 1) s += __shfl_xor_sync(0xffffffff, s, o);
        if (lane == 0) { sM[a] = m; sSum[a] = s; }
    }
    __syncthreads();

    if (tid < DA) {
        size_t pi = ((size_t)t * BATCH * NH + bh) * DA + tid;
        g_pm[pi] = sM[tid];
        g_ps[pi] = sSum[tid];
    }

    // raw partial AVp[a][d] = sum_n exp * v  (warp owns one agent at a time; lane owns d-pair)
    {
        const u64* vb = (const u64*)(sm + AP_SVT) + lane;   // [n][2*lane] at n*34 + lane
        for (int a = warp; a < DA; a += 8) {
            u64 acc = 0;
#pragma unroll 4
            for (int n = 0; n < TILE; n++) {
                float p = sm[AP_SS + n * 53 + a];
                fma2(acc, pack2(p, p), vb[n * 34]);
            }
            float2 f = unpack2(acc);
            size_t oi = (((size_t)t * BATCH * NH + bh) * DA + a) * HD + 2 * lane;
            g_avp[oi]     = f.x;
            g_avp[oi + 1] = f.y;
        }
    }
}

// ======================= agent attention combine =======================
// grid (NH, BATCH), 256 threads
__global__ void agent_combine()
{
    __shared__ float sW[NTILE * DA];
    __shared__ float sInv[DA];
    const int h = blockIdx.x, b = blockIdx.y;
    const int bh = b * NH + h;
    const int tid = threadIdx.x;

    if (tid < DA) {
        float mt[NTILE];
        float m = -1e30f;
#pragma unroll
        for (int t = 0; t < NTILE; t++) {
            mt[t] = g_pm[((size_t)t * BATCH * NH + bh) * DA + tid];
            m = fmaxf(m, mt[t]);
        }
        float s = 0.f;
#pragma unroll
        for (int t = 0; t < NTILE; t++) {
            float w = __expf(mt[t] - m);
            sW[t * DA + tid] = w;
            s += g_ps[((size_t)t * BATCH * NH + bh) * DA + tid] * w;
        }
        sInv[tid] = 1.f / s;
    }
    __syncthreads();

    float* avT = g_avT + (size_t)bh * HD * DA;
    for (int i = tid; i < DA * HD; i += 256) {
        int a = i >> 6, d = i & 63;
        float acc = 0.f;
#pragma unroll
        for (int t = 0; t < NTILE; t++)
            acc += g_avp[(((size_t)t * BATCH * NH + bh) * DA + a) * HD + d] * sW[t * DA + a];
        avT[d * DA + a] = acc * sInv[a];
    }
}

// ======================= q attention via tensor cores =======================
#define QT_SQ   0
#define QT_SAG  (112 * 68)
#define QT_SAVT (QT_SAG + 56 * 68)
#define QT_SS   (QT_SAVT + 64 * 60)
#define QT_SINV (QT_SS + 112 * 60)
#define QT_SMEM_FLOATS (QT_SINV + 112)
#define QT_SMEM_BYTES (QT_SMEM_FLOATS * 4)

__global__ void __launch_bounds__(256, 2) q_attn_mma()
{
    extern __shared__ float sm[];
    const int tile = blockIdx.x, h = blockIdx.y, b = blockIdx.z;
    const int n0 = tile * 112;
    const int tid = threadIdx.x;
    const int lane = tid & 31, warp = tid >> 5;
    const int gid = lane >> 2, tig = lane & 3;

    const float* qpl = g_qh + ((size_t)(b * NH + h)) * NTOK * HD;
    const float* agp = g_ag + ((size_t)(b * NH + h)) * DA * HD;
    const float* avT = g_avT + ((size_t)(b * NH + h)) * HD * DA;

    uint32_t smem_base = (uint32_t)__cvta_generic_to_shared(sm);

    for (int i = tid; i < 112 * 16; i += 256) {
        int r = i >> 4, c = i & 15;
        cp_async16(smem_base + (uint32_t)(QT_SQ + r * 68 + c * 4) * 4,
                   qpl + (size_t)(n0 + r) * HD + c * 4);
    }
    for (int i = tid; i < DA * 16; i += 256) {
        int r = i >> 4, c = i & 15;
        cp_async16(smem_base + (uint32_t)(QT_SAG + r * 68 + c * 4) * 4,
                   agp + (size_t)r * HD + c * 4);
    }
    cp_commit();
    for (int i = tid; i < 7 * 68; i += 256)
        sm[QT_SAG + (DA + i / 68) * 68 + (i % 68)] = 0.f;
    for (int i = tid; i < 64 * 56; i += 256) {
        int r = i / 56, c = i % 56;
        sm[QT_SAVT + r * 60 + c] = (c < DA) ? avT[r * DA + c] : 0.f;
    }
    {
        const float* abp = g_agent_bias + ((size_t)h * NTOK + n0) * DA;
        for (int i = tid; i < 112 * 56; i += 256) {
            int r = i / 56, c = i % 56;
            sm[QT_SS + r * 60 + c] = (c < DA) ? abp[r * DA + c] : 0.f;
        }
    }
    cp_wait<0>();
    __syncthreads();

    if (warp < 7) {
        const int m0 = warp * 16;
        uint32_t af[8][4];
#pragma unroll
        for (int c = 0; c < 8; c++) {
            const float* r0 = sm + QT_SQ + (m0 + gid) * 68 + 8 * c + tig;
            const float* r1 = r0 + 8 * 68;
            af[c][0] = f2tf(r0[0]);
            af[c][1] = f2tf(r1[0]);
            af[c][2] = f2tf(r0[4]);
            af[c][3] = f2tf(r1[4]);
        }
#pragma unroll
        for (int j = 0; j < 7; j++) {
            float acc[4] = {0.f, 0.f, 0.f, 0.f};
#pragma unroll
            for (int c = 0; c < 8; c++) {
                uint32_t bf[2];
                const float* br = sm + QT_SAG + (8 * j + gid) * 68 + 8 * c + tig;
                bf[0] = f2tf(br[0]);
                bf[1] = f2tf(br[4]);
                mma_tf32(acc, af[c], bf);
            }
            int col = 8 * j + 2 * tig;
            float* s0 = sm + QT_SS + (m0 + gid) * 60 + col;
            float* s1 = s0 + 8 * 60;
            s0[0] += acc[0]; s0[1] += acc[1];
            s1[0] += acc[2]; s1[1] += acc[3];
        }
    }
    __syncthreads();

    if (tid < 112) {
        float* row = sm + QT_SS + tid * 60;
        float m = -1e30f;
        for (int a = 0; a < DA; a++) m = fmaxf(m, row[a]);
        float s = 0.f;
        for (int a = 0; a < DA; a++) { float e = __expf(row[a] - m); row[a] = e; s += e; }
#pragma unroll
        for (int a = DA; a < 56; a++) row[a] = 0.f;
        sm[QT_SINV + tid] = 1.f / s;
    }
    __syncthreads();

    if (warp < 7) {
        const int m0 = warp * 16;
        uint32_t af[7][4];
#pragma unroll
        for (int c = 0; c < 7; c++) {
            const float* r0 = sm + QT_SS + (m0 + gid) * 60 + 8 * c + tig;
            const float* r1 = r0 + 8 * 60;
            af[c][0] = f2tf(r0[0]);
            af[c][1] = f2tf(r1[0]);
            af[c][2] = f2tf(r0[4]);
            af[c][3] = f2tf(r1[4]);
        }
        float inv0 = sm[QT_SINV + m0 + gid];
        float inv8 = sm[QT_SINV + m0 + gid + 8];
        float* orow0 = g_attn + ((size_t)(b * NTOK + n0 + m0 + gid)) * DIM + h * HD;
        float* orow8 = orow0 + (size_t)8 * DIM;
#pragma unroll
        for (int j = 0; j < 8; j++) {
            float acc[4] = {0.f, 0.f, 0.f, 0.f};
#pragma unroll
            for (int c = 0; c < 7; c++) {
                uint32_t bf[2];
                const float* br = sm + QT_SAVT + (8 * j + gid) * 60 + 8 * c + tig;
                bf[0] = f2tf(br[0]);
                bf[1] = f2tf(br[4]);
                mma_tf32(acc, af[c], bf);
            }
            int col = 8 * j + 2 * tig;
            *(float2*)&orow0[col] = make_float2(acc[0] * inv0, acc[1] * inv0);
            *(float2*)&orow8[col] = make_float2(acc[2] * inv8, acc[3] * inv8);
        }
    }
}

// ======================= depthwise 3x3 conv on v, + attn, -> tf32 =======================
__global__ void dwc_add(const float* __restrict__ w, const float* __restrict__ bias)
{
    int n = blockIdx.x, b = blockIdx.y;
    int c = threadIdx.x;
    int h = c >> 6, d = c & 63;
    int i = n / WW, j = n % WW;
    const float* vpl = g_v + ((size_t)(b * NH + h)) * NTOK * HD + d;
    float acc = bias[c];
#pragma unroll
    for (int di = 0; di < 3; di++) {
        int ii = i + di - 1;
        if (ii < 0 || ii > HH - 1) continue;
#pragma unroll
        for (int dj = 0; dj < 3; dj++) {
            int jj = j + dj - 1;
            if (jj < 0 || jj > WW - 1) continue;
            acc = fmaf(w[c * 9 + di * 3 + dj], vpl[(size_t)(ii * WW + jj) * HD], acc);
        }
    }
    size_t idx = ((size_t)(b * NTOK + n)) * DIM + c;
    g_attn_t[idx] = f2tf(g_attn[idx] + acc);
}

// ======================= launch =======================
extern "C" void kernel_launch(void* const* d_in, const int* in_sizes, int n_in,
                              void* d_out, int out_size)
{
    const float* x       = (const float*)d_in[0];
    const float* q_w     = (const float*)d_in[1];
    const float* kv_w    = (const float*)d_in[2];
    const float* proj_w  = (const float*)d_in[3];
    const float* proj_b  = (const float*)d_in[4];
    const float* dwc_w   = (const float*)d_in[5];
    const float* dwc_b   = (const float*)d_in[6];
    const float* an_bias = (const float*)d_in[7];
    const float* na_bias = (const float*)d_in[8];
    const float* ah_bias = (const float*)d_in[9];
    const float* aw_bias = (const float*)d_in[10];
    const float* ha_bias = (const float*)d_in[11];
    const float* wa_bias = (const float*)d_in[12];
    float* out = (float*)d_out;

    cudaFuncSetAttribute(gemm_qkv,      cudaFuncAttributeMaxDynamicSharedMemorySize, GEMM_SMEM_BYTES);
    cudaFuncSetAttribute(gemm_proj,     cudaFuncAttributeMaxDynamicSharedMemorySize, GEMM_SMEM_BYTES);
    cudaFuncSetAttribute(agent_partial, cudaFuncAttributeMaxDynamicSharedMemorySize, AP_SMEM_BYTES);
    cudaFuncSetAttribute(q_attn_mma,    cudaFuncAttributeMaxDynamicSharedMemorySize, QT_SMEM_BYTES);

    // 1: convert operands to tf32
    cvt_all<<<dim3(512, 4), 256>>>((const float4*)x, (const float4*)q_w,
                                   (const float4*)kv_w, (const float4*)proj_w);
    // 2: merged QKV GEMM (head-planar epilogue)
    gemm_qkv<<<dim3(3 * DIM / 128, (BATCH * NTOK) / 128), 256, GEMM_SMEM_BYTES>>>();
    // 3: bias tables
    build_bias<<<NH * DA, NTOK>>>(an_bias, na_bias, ah_bias, aw_bias, ha_bias, wa_bias);
    // 4: pooled agents
    pool_agent<<<dim3(NH, BATCH), 256>>>();
    // 5: agent attention partials (flash-style split over 7 token tiles)
    agent_partial<<<dim3(NTILE, NH, BATCH), 256, AP_SMEM_BYTES>>>();
    // 6: combine partials -> agent_v transposed
    agent_combine<<<dim3(NH, BATCH), 256>>>();
    // 7: q attention via tensor cores
    q_attn_mma<<<dim3(7, NH, BATCH), 256, QT_SMEM_BYTES>>>();
    // 8: depthwise conv + add + tf32 convert
    dwc_add<<<dim3(NTOK, BATCH), DIM>>>(dwc_w, dwc_b);
    // 9: output projection
    gemm_proj<<<dim3(DIM / 128, (BATCH * NTOK) / 128), 256, GEMM_SMEM_BYTES>>>(proj_b, out);
}